// round 12
// baseline (speedup 1.0000x reference)
#include <cuda_runtime.h>
#include <cuda_bf16.h>
#include <mma.h>
#include <math.h>
#include <stdint.h>

using namespace nvcuda;

#define NN 50000
#define NE 800000
#define NDIM 8
#define EDIM 3
#define HID 256
#define NHEADS 4
#define HD 64
#define NLAYERS 3
#define NG 64
#define NEG_SLOPE 0.2f

// ---------------- scratch (device globals; no allocation allowed) ----------------
__device__ float g_bufA[NN * HID];
__device__ float g_bufB[NN * HID];
__device__ float g_hp[NN * HID];
__device__ float g_logit[NE * NHEADS];   // raw leaky-relu'd logits (alpha computed in aggregate)
__device__ float g_ssrc[NN * NHEADS];
__device__ float g_sdst[NN * NHEADS];
__device__ float g_m[NN * NHEADS];
__device__ float g_invden[NN * NHEADS];
__device__ int   g_rowstart[NN + 1];
__device__ int   g_cursor[NN];
__device__ int   g_perm[NE];
__device__ int   g_part[64];
__device__ float g_coef[EDIM * NHEADS];
__device__ int   g_gstart[NG + 1];
__device__ __nv_bfloat16 g_Wh[HID * HID];
__device__ __nv_bfloat16 g_Wl[HID * HID];

__device__ __forceinline__ float* selbuf(int s) { return s ? g_bufB : g_bufA; }
__device__ __forceinline__ float elu(float x) { return x > 0.f ? x : expf(x) - 1.f; }

// ---------------- W -> bf16 hi/lo split (once per layer) ----------------
__global__ void k_wsplit(const float* __restrict__ W) {
    int i = blockIdx.x * blockDim.x + threadIdx.x;
    if (i >= HID * HID) return;
    float w = W[i];
    __nv_bfloat16 h = __float2bfloat16(w);
    g_Wh[i] = h;
    g_Wl[i] = __float2bfloat16(w - __bfloat162float(h));
}

// ================= wmma bf16-split GEMM: g_hp = selbuf(asel) @ W + bias =================
// Block: 128 rows x 256 cols (full N), 8 warps (2x4), warp tile 64x64.
// 48 MMA per 16 ldmatrix per warp-k-iter (ratio 3.0 vs 2.0 before) -> less L1 traffic/MMA.
#define GM 128
#define GN 256
#define APAD 24    // A smem leading dim (bf16), 48B
#define BPAD 264   // B smem leading dim (bf16), 528B

__global__ void __launch_bounds__(256, 1) k_wmma_gemm(int asel, const float* __restrict__ bias) {
    const float* A = selbuf(asel);
    __shared__ __nv_bfloat16 Ah[GM * APAD], Al[GM * APAD];
    __shared__ __nv_bfloat16 Bh[16 * BPAD], Bl[16 * BPAD];
    __shared__ float biasT[16 * GN];

    int tid = threadIdx.x;
    int wid = tid >> 5;
    int wm = wid >> 2;           // 0..1 -> 64-row slab
    int wn = wid & 3;            // 0..3 -> 64-col slab
    int bm = blockIdx.x * GM;

    // A-load mapping: row = tid>>1 (0..127), 8 cols
    int arow = tid >> 1;
    int acq = (tid & 1) << 3;
    int agr = bm + arow;
    const float* aptr = (agr < NN) ? (A + (size_t)agr * HID + acq) : (const float*)0;
    // B-load mapping: row = tid>>4 (0..15), 16 cols
    int brow = tid >> 4;
    int bcb = (tid & 15) << 4;

    for (int i = tid; i < 16 * GN; i += 256) biasT[i] = bias[i & (GN - 1)];
    __syncthreads();

    wmma::fragment<wmma::accumulator, 16, 16, 16, float> acc[4][4];
#pragma unroll
    for (int i = 0; i < 4; i++)
#pragma unroll
        for (int j = 0; j < 4; j++)
            wmma::load_matrix_sync(acc[i][j], &biasT[wn * 64 + j * 16], GN, wmma::mem_row_major);

    for (int k0 = 0; k0 < HID; k0 += 16) {
        // ---- A tile 128x16 fp32 -> bf16 hi/lo
        {
            float4 v0 = make_float4(0.f, 0.f, 0.f, 0.f), v1 = v0;
            if (aptr) {
                v0 = *(const float4*)(aptr + k0);
                v1 = *(const float4*)(aptr + k0 + 4);
            }
            float vv[8] = {v0.x, v0.y, v0.z, v0.w, v1.x, v1.y, v1.z, v1.w};
            __nv_bfloat16 hh[8], ll[8];
#pragma unroll
            for (int q = 0; q < 8; q++) {
                hh[q] = __float2bfloat16(vv[q]);
                ll[q] = __float2bfloat16(vv[q] - __bfloat162float(hh[q]));
            }
            *(uint4*)(Ah + arow * APAD + acq) = *(uint4*)hh;
            *(uint4*)(Al + arow * APAD + acq) = *(uint4*)ll;
        }
        // ---- B tile 16x256 from preconverted bf16
        {
            size_t go = (size_t)(k0 + brow) * HID + bcb;
            *(uint4*)(Bh + brow * BPAD + bcb) = *(const uint4*)(g_Wh + go);
            *(uint4*)(Bh + brow * BPAD + bcb + 8) = *(const uint4*)(g_Wh + go + 8);
            *(uint4*)(Bl + brow * BPAD + bcb) = *(const uint4*)(g_Wl + go);
            *(uint4*)(Bl + brow * BPAD + bcb + 8) = *(const uint4*)(g_Wl + go + 8);
        }
        __syncthreads();

        wmma::fragment<wmma::matrix_b, 16, 16, 16, __nv_bfloat16, wmma::row_major> fbh[4], fbl[4];
#pragma unroll
        for (int j = 0; j < 4; j++) {
            wmma::load_matrix_sync(fbh[j], &Bh[wn * 64 + j * 16], BPAD);
            wmma::load_matrix_sync(fbl[j], &Bl[wn * 64 + j * 16], BPAD);
        }
#pragma unroll
        for (int i = 0; i < 4; i++) {
            wmma::fragment<wmma::matrix_a, 16, 16, 16, __nv_bfloat16, wmma::row_major> fah, fal;
            wmma::load_matrix_sync(fah, &Ah[(wm * 64 + i * 16) * APAD], APAD);
            wmma::load_matrix_sync(fal, &Al[(wm * 64 + i * 16) * APAD], APAD);
#pragma unroll
            for (int j = 0; j < 4; j++) {
                wmma::mma_sync(acc[i][j], fah, fbh[j], acc[i][j]);
                wmma::mma_sync(acc[i][j], fal, fbh[j], acc[i][j]);
                wmma::mma_sync(acc[i][j], fah, fbl[j], acc[i][j]);
            }
        }
        __syncthreads();
    }

#pragma unroll
    for (int i = 0; i < 4; i++) {
        int gr0 = bm + wm * 64 + i * 16;
        if (gr0 < NN) {  // NN % 16 == 0: tile fully in or out
#pragma unroll
            for (int j = 0; j < 4; j++)
                wmma::store_matrix_sync(g_hp + (size_t)gr0 * HID + wn * 64 + j * 16,
                                        acc[i][j], HID, wmma::mem_row_major);
        }
    }
}

// ---------------- CSR build ----------------
__global__ void k_zero_cursor() {
    int i = blockIdx.x * blockDim.x + threadIdx.x;
    if (i < NN) g_cursor[i] = 0;
}

__global__ void k_count_deg(const int* __restrict__ dst) {
    int e = blockIdx.x * blockDim.x + threadIdx.x;
    if (e < NE) atomicAdd(&g_cursor[dst[e]], 1);
}

__global__ void k_scan1() {
    __shared__ int sh[1024];
    int i = blockIdx.x * 1024 + threadIdx.x;
    int v = (i < NN) ? g_cursor[i] : 0;
    sh[threadIdx.x] = v;
    __syncthreads();
    for (int off = 1; off < 1024; off <<= 1) {
        int t = (threadIdx.x >= off) ? sh[threadIdx.x - off] : 0;
        __syncthreads();
        sh[threadIdx.x] += t;
        __syncthreads();
    }
    if (i < NN) g_rowstart[i] = sh[threadIdx.x] - v;
    if (threadIdx.x == 1023) g_part[blockIdx.x] = sh[1023];
}

__global__ void k_scan2(int nparts) {
    __shared__ int sh[64];
    int t = threadIdx.x;
    int v0 = (t < nparts) ? g_part[t] : 0;
    sh[t] = v0;
    __syncthreads();
    for (int off = 1; off < 64; off <<= 1) {
        int v = (t >= off) ? sh[t - off] : 0;
        __syncthreads();
        sh[t] += v;
        __syncthreads();
    }
    if (t < nparts) g_part[t] = sh[t] - v0;  // exclusive
}

__global__ void k_scan3() {
    int i = blockIdx.x * blockDim.x + threadIdx.x;
    if (i < NN) {
        int v = g_rowstart[i] + g_part[i >> 10];
        g_rowstart[i] = v;
        g_cursor[i] = v;
    }
    if (i == 0) g_rowstart[NN] = NE;
}

__global__ void k_scatter(const int* __restrict__ dst) {
    int e = blockIdx.x * blockDim.x + threadIdx.x;
    if (e < NE) {
        int d = dst[e];
        int pos = atomicAdd(&g_cursor[d], 1);
        g_perm[pos] = e;
    }
}

// ---------------- input projection + LN + ELU -> g_bufA ----------------
__global__ void k_input_proj(const float* __restrict__ x, const float* __restrict__ Win,
                             const float* __restrict__ bin, const float* __restrict__ lg,
                             const float* __restrict__ lb) {
    int n = blockIdx.x;
    int c = threadIdx.x;  // 256
    __shared__ float xs[NDIM];
    __shared__ float s1[256], s2[256];
    if (c < NDIM) xs[c] = x[n * NDIM + c];
    __syncthreads();
    float v = bin[c];
#pragma unroll
    for (int k = 0; k < NDIM; k++) v += xs[k] * Win[k * HID + c];
    s1[c] = v;
    s2[c] = v * v;
    __syncthreads();
    for (int off = 128; off > 0; off >>= 1) {
        if (c < off) { s1[c] += s1[c + off]; s2[c] += s2[c + off]; }
        __syncthreads();
    }
    float mean = s1[0] * (1.f / HID);
    float var = s2[0] * (1.f / HID) - mean * mean;
    float rs = rsqrtf(var + 1e-5f);
    float y = (v - mean) * rs * lg[c] + lb[c];
    g_bufA[n * HID + c] = elu(y);
}

// ---------------- per-layer tiny coef ----------------
__global__ void k_edge_coef(const float* __restrict__ We, const float* __restrict__ ae) {
    int w = threadIdx.x >> 5;
    int lane = threadIdx.x & 31;
    if (w >= EDIM * NHEADS) return;
    int k = w >> 2, h = w & 3;
    const float* wrow = We + k * HID + h * HD;
    const float* arow = ae + h * HD;
    float v = wrow[lane] * arow[lane] + wrow[lane + 32] * arow[lane + 32];
#pragma unroll
    for (int off = 16; off > 0; off >>= 1) v += __shfl_down_sync(0xffffffffu, v, off);
    if (lane == 0) g_coef[k * NHEADS + h] = v;
}

// ---------------- per-(node,head) attention dots on g_hp ----------------
__global__ void k_sdots(const float* __restrict__ a_s, const float* __restrict__ a_d) {
    int w = (blockIdx.x * blockDim.x + threadIdx.x) >> 5;
    int lane = threadIdx.x & 31;
    if (w >= NN * NHEADS) return;
    int n = w >> 2, h = w & 3;
    const float* row = g_hp + n * HID + h * HD;
    float r0 = row[lane], r1 = row[lane + 32];
    float v1 = r0 * a_s[h * HD + lane] + r1 * a_s[h * HD + lane + 32];
    float v2 = r0 * a_d[h * HD + lane] + r1 * a_d[h * HD + lane + 32];
#pragma unroll
    for (int off = 16; off > 0; off >>= 1) {
        v1 += __shfl_down_sync(0xffffffffu, v1, off);
        v2 += __shfl_down_sync(0xffffffffu, v2, off);
    }
    if (lane == 0) { g_ssrc[w] = v1; g_sdst[w] = v2; }
}

// ---------------- edge logits (leaky-relu'd), edge-parallel coalesced ----------------
__global__ void k_edge_logits(const int* __restrict__ src, const int* __restrict__ dst,
                              const float* __restrict__ ea) {
    int e = blockIdx.x * blockDim.x + threadIdx.x;
    if (e >= NE) return;
    int s = src[e], d = dst[e];
    float a0 = ea[e * 3 + 0], a1 = ea[e * 3 + 1], a2 = ea[e * 3 + 2];
    float4 sv = *(const float4*)&g_ssrc[s * NHEADS];
    float4 dv = *(const float4*)&g_sdst[d * NHEADS];
    float4 out;
    float* o = (float*)&out;
    const float* ss = (const float*)&sv;
    const float* dd = (const float*)&dv;
#pragma unroll
    for (int h = 0; h < NHEADS; h++) {
        float lg = ss[h] + dd[h] +
                   a0 * g_coef[0 * NHEADS + h] + a1 * g_coef[1 * NHEADS + h] +
                   a2 * g_coef[2 * NHEADS + h];
        o[h] = lg > 0.f ? lg : NEG_SLOPE * lg;
    }
    *(float4*)&g_logit[e * NHEADS] = out;
}

// ---------------- per-node softmax stats: warp-per-node ----------------
__global__ void k_node_stats() {
    int w = (blockIdx.x * blockDim.x + threadIdx.x) >> 5;
    int lane = threadIdx.x & 31;
    if (w >= NN) return;
    int s0 = g_rowstart[w], s1 = g_rowstart[w + 1];

    float4 mx = make_float4(-3.4e38f, -3.4e38f, -3.4e38f, -3.4e38f);
    for (int j = s0 + lane; j < s1; j += 32) {
        int e = g_perm[j];
        float4 lg = *(const float4*)&g_logit[e * NHEADS];
        mx.x = fmaxf(mx.x, lg.x); mx.y = fmaxf(mx.y, lg.y);
        mx.z = fmaxf(mx.z, lg.z); mx.w = fmaxf(mx.w, lg.w);
    }
#pragma unroll
    for (int off = 16; off > 0; off >>= 1) {
        mx.x = fmaxf(mx.x, __shfl_xor_sync(0xffffffffu, mx.x, off));
        mx.y = fmaxf(mx.y, __shfl_xor_sync(0xffffffffu, mx.y, off));
        mx.z = fmaxf(mx.z, __shfl_xor_sync(0xffffffffu, mx.z, off));
        mx.w = fmaxf(mx.w, __shfl_xor_sync(0xffffffffu, mx.w, off));
    }
    if (s0 == s1) mx = make_float4(0.f, 0.f, 0.f, 0.f);

    float4 den = make_float4(0.f, 0.f, 0.f, 0.f);
    for (int j = s0 + lane; j < s1; j += 32) {
        int e = g_perm[j];
        float4 lg = *(const float4*)&g_logit[e * NHEADS];
        den.x += expf(lg.x - mx.x); den.y += expf(lg.y - mx.y);
        den.z += expf(lg.z - mx.z); den.w += expf(lg.w - mx.w);
    }
#pragma unroll
    for (int off = 16; off > 0; off >>= 1) {
        den.x += __shfl_xor_sync(0xffffffffu, den.x, off);
        den.y += __shfl_xor_sync(0xffffffffu, den.y, off);
        den.z += __shfl_xor_sync(0xffffffffu, den.z, off);
        den.w += __shfl_xor_sync(0xffffffffu, den.w, off);
    }
    if (lane == 0) {
        *(float4*)&g_m[w * NHEADS] = mx;
        float4 inv;
        inv.x = 1.f / fmaxf(den.x, 1e-16f);
        inv.y = 1.f / fmaxf(den.y, 1e-16f);
        inv.z = 1.f / fmaxf(den.z, 1e-16f);
        inv.w = 1.f / fmaxf(den.w, 1e-16f);
        *(float4*)&g_invden[w * NHEADS] = inv;
    }
}

// ---------------- staged aggregation (alpha fused): 4 nodes/block, 64 threads/node ----------------
#define ECH 64
__global__ void __launch_bounds__(256) k_aggregate(int insel, int outsel,
                                                   const int* __restrict__ src) {
    const float* hin = selbuf(insel);
    float* hout = selbuf(outsel);
    __shared__ int s_src[4][ECH];
    __shared__ float s_al[4][ECH * 4];
    __shared__ int s_deg[4];

    int tid = threadIdx.x;
    int slot = tid >> 6;
    int lt = tid & 63;
    int n = blockIdx.x * 4 + slot;   // NN % 4 == 0

    int s0 = g_rowstart[n], s1 = g_rowstart[n + 1];
    int deg = s1 - s0;
    if (lt == 0) s_deg[slot] = deg;
    float4 m4 = *(const float4*)&g_m[n * NHEADS];
    float4 iv4 = *(const float4*)&g_invden[n * NHEADS];
    __syncthreads();
    int maxdeg = max(max(s_deg[0], s_deg[1]), max(s_deg[2], s_deg[3]));

    int h = lt >> 4;                 // head for cols [lt*4, lt*4+4)
    float4 acc = make_float4(0.f, 0.f, 0.f, 0.f);

    for (int base = 0; base < maxdeg; base += ECH) {
        int cnt = min(ECH, deg - base);
        if (lt < cnt) {
            int e = g_perm[s0 + base + lt];
            s_src[slot][lt] = src[e];
            float4 lg = *(const float4*)&g_logit[e * NHEADS];
            float4 a;
            a.x = expf(lg.x - m4.x) * iv4.x;
            a.y = expf(lg.y - m4.y) * iv4.y;
            a.z = expf(lg.z - m4.z) * iv4.z;
            a.w = expf(lg.w - m4.w) * iv4.w;
            *(float4*)&s_al[slot][lt * 4] = a;
        }
        __syncthreads();
#pragma unroll 4
        for (int j = 0; j < cnt; j++) {
            int s = s_src[slot][j];
            float a = s_al[slot][j * 4 + h];
            float4 hv = *(const float4*)&g_hp[(size_t)s * HID + lt * 4];
            acc.x += a * hv.x; acc.y += a * hv.y;
            acc.z += a * hv.z; acc.w += a * hv.w;
        }
        __syncthreads();
    }

    float4 r = *(const float4*)&hin[(size_t)n * HID + lt * 4];
    float4 o;
    o.x = elu(acc.x + r.x); o.y = elu(acc.y + r.y);
    o.z = elu(acc.z + r.z); o.w = elu(acc.w + r.w);
    *(float4*)&hout[(size_t)n * HID + lt * 4] = o;
}

// ---------------- output LN + ELU, write node_emb ----------------
__global__ void k_ln_out(const float* __restrict__ lg, const float* __restrict__ lb,
                         float* __restrict__ outp, int fallback_sel) {
    float* o = outp ? outp : selbuf(fallback_sel);
    int n = blockIdx.x;
    int c = threadIdx.x;
    __shared__ float s1[256], s2[256];
    float v = g_hp[n * HID + c];
    s1[c] = v;
    s2[c] = v * v;
    __syncthreads();
    for (int off = 128; off > 0; off >>= 1) {
        if (c < off) { s1[c] += s1[c + off]; s2[c] += s2[c + off]; }
        __syncthreads();
    }
    float mean = s1[0] * (1.f / HID);
    float var = s2[0] * (1.f / HID) - mean * mean;
    float rs = rsqrtf(var + 1e-5f);
    float y = (v - mean) * rs * lg[c] + lb[c];
    o[n * HID + c] = elu(y);
}

// ---------------- pooling ----------------
__global__ void k_graph_starts(const int* __restrict__ batch) {
    int n = blockIdx.x * blockDim.x + threadIdx.x;
    if (n >= NN) return;
    int b = batch[n];
    int bp = (n == 0) ? -1 : batch[n - 1];
    for (int g = bp + 1; g <= b; g++) g_gstart[g] = n;
    if (n == NN - 1)
        for (int g = b + 1; g <= NG; g++) g_gstart[g] = NN;
}

__global__ void k_zero_float(float* p, int n) {
    int i = blockIdx.x * blockDim.x + threadIdx.x;
    if (i < n) p[i] = 0.f;
}

__global__ void k_pool_partial(const float* __restrict__ embp, int fallback_sel,
                               float* __restrict__ out) {
    const float* emb = embp ? embp : selbuf(fallback_sel);
    int g = blockIdx.x;
    int part = blockIdx.y;
    int c = threadIdx.x;
    int s = g_gstart[g], e = g_gstart[g + 1];
    int cnt = e - s;
    if (cnt <= 0) return;
    int chunk = (cnt + gridDim.y - 1) / gridDim.y;
    int ps = s + part * chunk;
    int pe = min(ps + chunk, e);
    if (ps >= pe) return;
    float acc = 0.f;
    for (int n = ps; n < pe; n++) acc += emb[n * HID + c];
    atomicAdd(&out[g * HID + c], acc);
}

__global__ void k_pool_final(float* __restrict__ out) {
    int g = blockIdx.x;
    int c = threadIdx.x;
    float cnt = (float)(g_gstart[g + 1] - g_gstart[g]);
    out[g * HID + c] /= fmaxf(cnt, 1.f);
}

// ---------------- launch ----------------
extern "C" void kernel_launch(void* const* d_in, const int* in_sizes, int n_in,
                              void* d_out, int out_size) {
    const float* x = (const float*)d_in[0];
    const int* edge_index = (const int*)d_in[1];   // int32
    const float* edge_attr = (const float*)d_in[2];
    const int* batch = (const int*)d_in[3];        // int32
    const float* x_W_in = (const float*)d_in[4];
    const float* b_in = (const float*)d_in[5];
    const float* ln_in_g = (const float*)d_in[6];
    const float* ln_in_b = (const float*)d_in[7];
    const float* W_gat = (const float*)d_in[8];
    const float* b_gat = (const float*)d_in[9];
    const float* W_e = (const float*)d_in[10];
    const float* a_src = (const float*)d_in[11];
    const float* a_dst = (const float*)d_in[12];
    const float* a_edge = (const float*)d_in[13];
    const float* W_out = (const float*)d_in[14];
    const float* b_out = (const float*)d_in[15];
    const float* ln_out_g = (const float*)d_in[16];
    const float* ln_out_b = (const float*)d_in[17];

    const int* src = edge_index;
    const int* dst = edge_index + NE;

    float* out = (float*)d_out;
    float* graph_out = nullptr;
    float* node_out = nullptr;
    if (out_size >= NG * HID + NN * HID) {
        graph_out = out;
        node_out = out + NG * HID;
    } else if (out_size >= NN * HID) {
        node_out = out;
    } else {
        graph_out = out;
    }

    const int EB = (NE + 255) / 256;
    const int NB = (NN + 255) / 256;
    const int NPARTS = (NN + 1023) / 1024;  // 49
    const int WS_B = (HID * HID + 255) / 256;
    const int GEMM_BLOCKS = (NN + GM - 1) / GM;  // 391

    // Launch order keeps layer-0 k_wmma_gemm at index 3 (ncu window).
    k_input_proj<<<NN, 256>>>(x, x_W_in, b_in, ln_in_g, ln_in_b);   // 0
    k_zero_cursor<<<NB, 256>>>();                                    // 1
    k_wsplit<<<WS_B, 256>>>(W_gat);                                  // 2 (layer 0 W)
    k_wmma_gemm<<<GEMM_BLOCKS, 256>>>(0, b_gat);                     // 3 (layer 0)
    k_count_deg<<<EB, 256>>>(dst);                                   // 4
    k_scan1<<<NPARTS, 1024>>>();                                     // 5
    k_scan2<<<1, 64>>>(NPARTS);                                      // 6
    k_scan3<<<NB, 256>>>();                                          // 7
    k_scatter<<<EB, 256>>>(dst);                                     // 8

    int cur = 0;  // 0 = bufA, 1 = bufB
    for (int l = 0; l < NLAYERS; l++) {
        int nxt = 1 - cur;
        const float* Wl = W_gat + l * HID * HID;
        const float* bl = b_gat + l * HID;
        const float* Wel = W_e + l * EDIM * HID;
        const float* asl = a_src + l * NHEADS * HD;
        const float* adl = a_dst + l * NHEADS * HD;
        const float* ael = a_edge + l * NHEADS * HD;

        if (l > 0) {
            k_wsplit<<<WS_B, 256>>>(Wl);
            k_wmma_gemm<<<GEMM_BLOCKS, 256>>>(cur, bl);
        }
        k_edge_coef<<<1, 384>>>(Wel, ael);
        k_sdots<<<(NN * NHEADS + 7) / 8, 256>>>(asl, adl);
        k_edge_logits<<<EB, 256>>>(src, dst, edge_attr);
        k_node_stats<<<(NN + 7) / 8, 256>>>();
        k_aggregate<<<NN / 4, 256>>>(cur, nxt, src);
        cur = nxt;
    }

    // ---- output projection + LN + ELU ----
    k_wsplit<<<WS_B, 256>>>(W_out);
    k_wmma_gemm<<<GEMM_BLOCKS, 256>>>(cur, b_out);
    int fsel = 1 - cur;
    k_ln_out<<<NN, 256>>>(ln_out_g, ln_out_b, node_out, fsel);

    // ---- global mean pool ----
    if (graph_out) {
        k_graph_starts<<<NB, 256>>>(batch);
        k_zero_float<<<(NG * HID + 255) / 256, 256>>>(graph_out, NG * HID);
        dim3 pg(NG, 16);
        k_pool_partial<<<pg, 256>>>(node_out, fsel, graph_out);
        k_pool_final<<<NG, 256>>>(graph_out);
    }
}

// round 13
// speedup vs baseline: 1.0464x; 1.0464x over previous
#include <cuda_runtime.h>
#include <cuda_bf16.h>
#include <mma.h>
#include <math.h>
#include <stdint.h>

using namespace nvcuda;

#define NN 50000
#define NE 800000
#define NDIM 8
#define EDIM 3
#define HID 256
#define NHEADS 4
#define HD 64
#define NLAYERS 3
#define NG 64
#define NEG_SLOPE 0.2f

// ---------------- scratch (device globals; no allocation allowed) ----------------
__device__ float g_bufA[NN * HID];
__device__ float g_bufB[NN * HID];
__device__ float g_hp[NN * HID];
__device__ float g_logit[NE * NHEADS];   // CSR-ordered leaky-relu'd logits
__device__ float g_ssrc[NN * NHEADS];
__device__ float g_sdst[NN * NHEADS];
__device__ float g_m[NN * NHEADS];
__device__ float g_invden[NN * NHEADS];
__device__ int   g_rowstart[NN + 1];
__device__ int   g_cursor[NN];
__device__ int   g_inv[NE];              // edge -> CSR position
__device__ int   g_psrc[NE];             // CSR-ordered src node ids
__device__ int   g_part[64];
__device__ float g_coef[EDIM * NHEADS];
__device__ int   g_gstart[NG + 1];
__device__ __nv_bfloat16 g_Wh[HID * HID];
__device__ __nv_bfloat16 g_Wl[HID * HID];

__device__ __forceinline__ float* selbuf(int s) { return s ? g_bufB : g_bufA; }
__device__ __forceinline__ float elu(float x) { return x > 0.f ? x : expf(x) - 1.f; }

// ---------------- W -> bf16 hi/lo split (once per layer) ----------------
__global__ void k_wsplit(const float* __restrict__ W) {
    int i = blockIdx.x * blockDim.x + threadIdx.x;
    if (i >= HID * HID) return;
    float w = W[i];
    __nv_bfloat16 h = __float2bfloat16(w);
    g_Wh[i] = h;
    g_Wl[i] = __float2bfloat16(w - __bfloat162float(h));
}

// ================= wmma bf16-split GEMM (R9 best config): g_hp = selbuf(asel) @ W + bias ======
#define GM 64
#define GN 128
#define APAD 24    // 48B stride
#define BPAD 136   // 272B stride

__global__ void __launch_bounds__(128, 3) k_wmma_gemm(int asel, const float* __restrict__ bias) {
    const float* A = selbuf(asel);
    __shared__ __nv_bfloat16 Ah[GM * APAD], Al[GM * APAD];
    __shared__ __nv_bfloat16 Bh[16 * BPAD], Bl[16 * BPAD];
    __shared__ float biasT[16 * GN];

    int tid = threadIdx.x;
    int wid = tid >> 5;
    int wm = wid >> 1;           // 0..1 -> 32-row slab
    int wn = wid & 1;            // 0..1 -> 64-col slab
    int bm = blockIdx.x * GM;
    int bn = blockIdx.y * GN;

    for (int i = tid; i < 16 * GN; i += 128) biasT[i] = bias[bn + (i & (GN - 1))];
    __syncthreads();

    wmma::fragment<wmma::accumulator, 16, 16, 16, float> acc[2][4];
#pragma unroll
    for (int i = 0; i < 2; i++)
#pragma unroll
        for (int j = 0; j < 4; j++)
            wmma::load_matrix_sync(acc[i][j], &biasT[wn * 64 + j * 16], GN, wmma::mem_row_major);

    for (int k0 = 0; k0 < HID; k0 += 16) {
        {
            int row = tid >> 1;
            int cq = (tid & 1) << 3;
            int gr = bm + row;
            float4 v0 = make_float4(0.f, 0.f, 0.f, 0.f), v1 = v0;
            if (gr < NN) {
                const float* ap = A + (size_t)gr * HID + k0 + cq;
                v0 = *(const float4*)ap;
                v1 = *(const float4*)(ap + 4);
            }
            __nv_bfloat16 hh[8], ll[8];
            float vv[8] = {v0.x, v0.y, v0.z, v0.w, v1.x, v1.y, v1.z, v1.w};
#pragma unroll
            for (int q = 0; q < 8; q++) {
                hh[q] = __float2bfloat16(vv[q]);
                ll[q] = __float2bfloat16(vv[q] - __bfloat162float(hh[q]));
            }
            *(uint4*)(Ah + row * APAD + cq) = *(uint4*)hh;
            *(uint4*)(Al + row * APAD + cq) = *(uint4*)ll;
        }
        {
            int row = tid >> 3;
            int cb = (tid & 7) << 4;
            size_t go = (size_t)(k0 + row) * HID + bn + cb;
            *(uint4*)(Bh + row * BPAD + cb) = *(const uint4*)(g_Wh + go);
            *(uint4*)(Bh + row * BPAD + cb + 8) = *(const uint4*)(g_Wh + go + 8);
            *(uint4*)(Bl + row * BPAD + cb) = *(const uint4*)(g_Wl + go);
            *(uint4*)(Bl + row * BPAD + cb + 8) = *(const uint4*)(g_Wl + go + 8);
        }
        __syncthreads();

        wmma::fragment<wmma::matrix_b, 16, 16, 16, __nv_bfloat16, wmma::row_major> fbh[4], fbl[4];
#pragma unroll
        for (int j = 0; j < 4; j++) {
            wmma::load_matrix_sync(fbh[j], &Bh[wn * 64 + j * 16], BPAD);
            wmma::load_matrix_sync(fbl[j], &Bl[wn * 64 + j * 16], BPAD);
        }
#pragma unroll
        for (int i = 0; i < 2; i++) {
            wmma::fragment<wmma::matrix_a, 16, 16, 16, __nv_bfloat16, wmma::row_major> fah, fal;
            wmma::load_matrix_sync(fah, &Ah[(wm * 32 + i * 16) * APAD], APAD);
            wmma::load_matrix_sync(fal, &Al[(wm * 32 + i * 16) * APAD], APAD);
#pragma unroll
            for (int j = 0; j < 4; j++) {
                wmma::mma_sync(acc[i][j], fah, fbh[j], acc[i][j]);
                wmma::mma_sync(acc[i][j], fal, fbh[j], acc[i][j]);
                wmma::mma_sync(acc[i][j], fah, fbl[j], acc[i][j]);
            }
        }
        __syncthreads();
    }

#pragma unroll
    for (int i = 0; i < 2; i++) {
        int gr0 = bm + wm * 32 + i * 16;
        if (gr0 < NN) {  // NN % 16 == 0
#pragma unroll
            for (int j = 0; j < 4; j++)
                wmma::store_matrix_sync(g_hp + (size_t)gr0 * HID + bn + wn * 64 + j * 16,
                                        acc[i][j], HID, wmma::mem_row_major);
        }
    }
}

// ---------------- CSR build ----------------
__global__ void k_zero_cursor() {
    int i = blockIdx.x * blockDim.x + threadIdx.x;
    if (i < NN) g_cursor[i] = 0;
}

__global__ void k_count_deg(const int* __restrict__ dst) {
    int e = blockIdx.x * blockDim.x + threadIdx.x;
    if (e < NE) atomicAdd(&g_cursor[dst[e]], 1);
}

__global__ void k_scan1() {
    __shared__ int sh[1024];
    int i = blockIdx.x * 1024 + threadIdx.x;
    int v = (i < NN) ? g_cursor[i] : 0;
    sh[threadIdx.x] = v;
    __syncthreads();
    for (int off = 1; off < 1024; off <<= 1) {
        int t = (threadIdx.x >= off) ? sh[threadIdx.x - off] : 0;
        __syncthreads();
        sh[threadIdx.x] += t;
        __syncthreads();
    }
    if (i < NN) g_rowstart[i] = sh[threadIdx.x] - v;
    if (threadIdx.x == 1023) g_part[blockIdx.x] = sh[1023];
}

__global__ void k_scan2(int nparts) {
    __shared__ int sh[64];
    int t = threadIdx.x;
    int v0 = (t < nparts) ? g_part[t] : 0;
    sh[t] = v0;
    __syncthreads();
    for (int off = 1; off < 64; off <<= 1) {
        int v = (t >= off) ? sh[t - off] : 0;
        __syncthreads();
        sh[t] += v;
        __syncthreads();
    }
    if (t < nparts) g_part[t] = sh[t] - v0;  // exclusive
}

__global__ void k_scan3() {
    int i = blockIdx.x * blockDim.x + threadIdx.x;
    if (i < NN) {
        int v = g_rowstart[i] + g_part[i >> 10];
        g_rowstart[i] = v;
        g_cursor[i] = v;
    }
    if (i == 0) g_rowstart[NN] = NE;
}

// scatter: record inverse perm and CSR-ordered src
__global__ void k_scatter(const int* __restrict__ src, const int* __restrict__ dst) {
    int e = blockIdx.x * blockDim.x + threadIdx.x;
    if (e < NE) {
        int d = dst[e];
        int pos = atomicAdd(&g_cursor[d], 1);
        g_inv[e] = pos;
        g_psrc[pos] = src[e];
    }
}

// ---------------- input projection + LN + ELU -> g_bufA ----------------
__global__ void k_input_proj(const float* __restrict__ x, const float* __restrict__ Win,
                             const float* __restrict__ bin, const float* __restrict__ lg,
                             const float* __restrict__ lb) {
    int n = blockIdx.x;
    int c = threadIdx.x;  // 256
    __shared__ float xs[NDIM];
    __shared__ float s1[256], s2[256];
    if (c < NDIM) xs[c] = x[n * NDIM + c];
    __syncthreads();
    float v = bin[c];
#pragma unroll
    for (int k = 0; k < NDIM; k++) v += xs[k] * Win[k * HID + c];
    s1[c] = v;
    s2[c] = v * v;
    __syncthreads();
    for (int off = 128; off > 0; off >>= 1) {
        if (c < off) { s1[c] += s1[c + off]; s2[c] += s2[c + off]; }
        __syncthreads();
    }
    float mean = s1[0] * (1.f / HID);
    float var = s2[0] * (1.f / HID) - mean * mean;
    float rs = rsqrtf(var + 1e-5f);
    float y = (v - mean) * rs * lg[c] + lb[c];
    g_bufA[n * HID + c] = elu(y);
}

// ---------------- per-layer tiny coef ----------------
__global__ void k_edge_coef(const float* __restrict__ We, const float* __restrict__ ae) {
    int w = threadIdx.x >> 5;
    int lane = threadIdx.x & 31;
    if (w >= EDIM * NHEADS) return;
    int k = w >> 2, h = w & 3;
    const float* wrow = We + k * HID + h * HD;
    const float* arow = ae + h * HD;
    float v = wrow[lane] * arow[lane] + wrow[lane + 32] * arow[lane + 32];
#pragma unroll
    for (int off = 16; off > 0; off >>= 1) v += __shfl_down_sync(0xffffffffu, v, off);
    if (lane == 0) g_coef[k * NHEADS + h] = v;
}

// ---------------- per-(node,head) attention dots on g_hp ----------------
__global__ void k_sdots(const float* __restrict__ a_s, const float* __restrict__ a_d) {
    int w = (blockIdx.x * blockDim.x + threadIdx.x) >> 5;
    int lane = threadIdx.x & 31;
    if (w >= NN * NHEADS) return;
    int n = w >> 2, h = w & 3;
    const float* row = g_hp + n * HID + h * HD;
    float r0 = row[lane], r1 = row[lane + 32];
    float v1 = r0 * a_s[h * HD + lane] + r1 * a_s[h * HD + lane + 32];
    float v2 = r0 * a_d[h * HD + lane] + r1 * a_d[h * HD + lane + 32];
#pragma unroll
    for (int off = 16; off > 0; off >>= 1) {
        v1 += __shfl_down_sync(0xffffffffu, v1, off);
        v2 += __shfl_down_sync(0xffffffffu, v2, off);
    }
    if (lane == 0) { g_ssrc[w] = v1; g_sdst[w] = v2; }
}

// ---------------- edge logits -> CSR-ordered slots (coalesced reads, scattered store) ----------
__global__ void k_edge_logits(const int* __restrict__ src, const int* __restrict__ dst,
                              const float* __restrict__ ea) {
    int e = blockIdx.x * blockDim.x + threadIdx.x;
    if (e >= NE) return;
    int s = src[e], d = dst[e];
    int pos = g_inv[e];
    float a0 = ea[e * 3 + 0], a1 = ea[e * 3 + 1], a2 = ea[e * 3 + 2];
    float4 sv = *(const float4*)&g_ssrc[s * NHEADS];
    float4 dv = *(const float4*)&g_sdst[d * NHEADS];
    float4 out;
    float* o = (float*)&out;
    const float* ss = (const float*)&sv;
    const float* dd = (const float*)&dv;
#pragma unroll
    for (int h = 0; h < NHEADS; h++) {
        float lg = ss[h] + dd[h] +
                   a0 * g_coef[0 * NHEADS + h] + a1 * g_coef[1 * NHEADS + h] +
                   a2 * g_coef[2 * NHEADS + h];
        o[h] = lg > 0.f ? lg : NEG_SLOPE * lg;
    }
    *(float4*)&g_logit[(size_t)pos * NHEADS] = out;
}

// ---------------- per-node softmax stats: warp-per-node, contiguous logit stream ----------------
__global__ void k_node_stats() {
    int w = (blockIdx.x * blockDim.x + threadIdx.x) >> 5;
    int lane = threadIdx.x & 31;
    if (w >= NN) return;
    int s0 = g_rowstart[w], s1 = g_rowstart[w + 1];

    float4 mx = make_float4(-3.4e38f, -3.4e38f, -3.4e38f, -3.4e38f);
    for (int j = s0 + lane; j < s1; j += 32) {
        float4 lg = *(const float4*)&g_logit[(size_t)j * NHEADS];
        mx.x = fmaxf(mx.x, lg.x); mx.y = fmaxf(mx.y, lg.y);
        mx.z = fmaxf(mx.z, lg.z); mx.w = fmaxf(mx.w, lg.w);
    }
#pragma unroll
    for (int off = 16; off > 0; off >>= 1) {
        mx.x = fmaxf(mx.x, __shfl_xor_sync(0xffffffffu, mx.x, off));
        mx.y = fmaxf(mx.y, __shfl_xor_sync(0xffffffffu, mx.y, off));
        mx.z = fmaxf(mx.z, __shfl_xor_sync(0xffffffffu, mx.z, off));
        mx.w = fmaxf(mx.w, __shfl_xor_sync(0xffffffffu, mx.w, off));
    }
    if (s0 == s1) mx = make_float4(0.f, 0.f, 0.f, 0.f);

    float4 den = make_float4(0.f, 0.f, 0.f, 0.f);
    for (int j = s0 + lane; j < s1; j += 32) {
        float4 lg = *(const float4*)&g_logit[(size_t)j * NHEADS];
        den.x += expf(lg.x - mx.x); den.y += expf(lg.y - mx.y);
        den.z += expf(lg.z - mx.z); den.w += expf(lg.w - mx.w);
    }
#pragma unroll
    for (int off = 16; off > 0; off >>= 1) {
        den.x += __shfl_xor_sync(0xffffffffu, den.x, off);
        den.y += __shfl_xor_sync(0xffffffffu, den.y, off);
        den.z += __shfl_xor_sync(0xffffffffu, den.z, off);
        den.w += __shfl_xor_sync(0xffffffffu, den.w, off);
    }
    if (lane == 0) {
        *(float4*)&g_m[w * NHEADS] = mx;
        float4 inv;
        inv.x = 1.f / fmaxf(den.x, 1e-16f);
        inv.y = 1.f / fmaxf(den.y, 1e-16f);
        inv.z = 1.f / fmaxf(den.z, 1e-16f);
        inv.w = 1.f / fmaxf(den.w, 1e-16f);
        *(float4*)&g_invden[w * NHEADS] = inv;
    }
}

// ---------------- staged aggregation: contiguous psrc/logit streams, random hp gathers ----------
#define ECH 64
__global__ void __launch_bounds__(256) k_aggregate(int insel, int outsel) {
    const float* hin = selbuf(insel);
    float* hout = selbuf(outsel);
    __shared__ int s_src[4][ECH];
    __shared__ float s_al[4][ECH * 4];
    __shared__ int s_deg[4];

    int tid = threadIdx.x;
    int slot = tid >> 6;
    int lt = tid & 63;
    int n = blockIdx.x * 4 + slot;   // NN % 4 == 0

    int s0 = g_rowstart[n], s1 = g_rowstart[n + 1];
    int deg = s1 - s0;
    if (lt == 0) s_deg[slot] = deg;
    float4 m4 = *(const float4*)&g_m[n * NHEADS];
    float4 iv4 = *(const float4*)&g_invden[n * NHEADS];
    __syncthreads();
    int maxdeg = max(max(s_deg[0], s_deg[1]), max(s_deg[2], s_deg[3]));

    int h = lt >> 4;                 // head for cols [lt*4, lt*4+4)
    float4 acc = make_float4(0.f, 0.f, 0.f, 0.f);

    for (int base = 0; base < maxdeg; base += ECH) {
        int cnt = min(ECH, deg - base);
        if (lt < cnt) {
            int j = s0 + base + lt;
            s_src[slot][lt] = g_psrc[j];
            float4 lg = *(const float4*)&g_logit[(size_t)j * NHEADS];
            float4 a;
            a.x = expf(lg.x - m4.x) * iv4.x;
            a.y = expf(lg.y - m4.y) * iv4.y;
            a.z = expf(lg.z - m4.z) * iv4.z;
            a.w = expf(lg.w - m4.w) * iv4.w;
            *(float4*)&s_al[slot][lt * 4] = a;
        }
        __syncthreads();
#pragma unroll 4
        for (int j = 0; j < cnt; j++) {
            int s = s_src[slot][j];
            float a = s_al[slot][j * 4 + h];
            float4 hv = *(const float4*)&g_hp[(size_t)s * HID + lt * 4];
            acc.x += a * hv.x; acc.y += a * hv.y;
            acc.z += a * hv.z; acc.w += a * hv.w;
        }
        __syncthreads();
    }

    float4 r = *(const float4*)&hin[(size_t)n * HID + lt * 4];
    float4 o;
    o.x = elu(acc.x + r.x); o.y = elu(acc.y + r.y);
    o.z = elu(acc.z + r.z); o.w = elu(acc.w + r.w);
    *(float4*)&hout[(size_t)n * HID + lt * 4] = o;
}

// ---------------- output LN + ELU, write node_emb ----------------
__global__ void k_ln_out(const float* __restrict__ lg, const float* __restrict__ lb,
                         float* __restrict__ outp, int fallback_sel) {
    float* o = outp ? outp : selbuf(fallback_sel);
    int n = blockIdx.x;
    int c = threadIdx.x;
    __shared__ float s1[256], s2[256];
    float v = g_hp[n * HID + c];
    s1[c] = v;
    s2[c] = v * v;
    __syncthreads();
    for (int off = 128; off > 0; off >>= 1) {
        if (c < off) { s1[c] += s1[c + off]; s2[c] += s2[c + off]; }
        __syncthreads();
    }
    float mean = s1[0] * (1.f / HID);
    float var = s2[0] * (1.f / HID) - mean * mean;
    float rs = rsqrtf(var + 1e-5f);
    float y = (v - mean) * rs * lg[c] + lb[c];
    o[n * HID + c] = elu(y);
}

// ---------------- pooling ----------------
__global__ void k_graph_starts(const int* __restrict__ batch) {
    int n = blockIdx.x * blockDim.x + threadIdx.x;
    if (n >= NN) return;
    int b = batch[n];
    int bp = (n == 0) ? -1 : batch[n - 1];
    for (int g = bp + 1; g <= b; g++) g_gstart[g] = n;
    if (n == NN - 1)
        for (int g = b + 1; g <= NG; g++) g_gstart[g] = NN;
}

__global__ void k_zero_float(float* p, int n) {
    int i = blockIdx.x * blockDim.x + threadIdx.x;
    if (i < n) p[i] = 0.f;
}

__global__ void k_pool_partial(const float* __restrict__ embp, int fallback_sel,
                               float* __restrict__ out) {
    const float* emb = embp ? embp : selbuf(fallback_sel);
    int g = blockIdx.x;
    int part = blockIdx.y;
    int c = threadIdx.x;
    int s = g_gstart[g], e = g_gstart[g + 1];
    int cnt = e - s;
    if (cnt <= 0) return;
    int chunk = (cnt + gridDim.y - 1) / gridDim.y;
    int ps = s + part * chunk;
    int pe = min(ps + chunk, e);
    if (ps >= pe) return;
    float acc = 0.f;
    for (int n = ps; n < pe; n++) acc += emb[n * HID + c];
    atomicAdd(&out[g * HID + c], acc);
}

__global__ void k_pool_final(float* __restrict__ out) {
    int g = blockIdx.x;
    int c = threadIdx.x;
    float cnt = (float)(g_gstart[g + 1] - g_gstart[g]);
    out[g * HID + c] /= fmaxf(cnt, 1.f);
}

// ---------------- launch ----------------
extern "C" void kernel_launch(void* const* d_in, const int* in_sizes, int n_in,
                              void* d_out, int out_size) {
    const float* x = (const float*)d_in[0];
    const int* edge_index = (const int*)d_in[1];   // int32
    const float* edge_attr = (const float*)d_in[2];
    const int* batch = (const int*)d_in[3];        // int32
    const float* x_W_in = (const float*)d_in[4];
    const float* b_in = (const float*)d_in[5];
    const float* ln_in_g = (const float*)d_in[6];
    const float* ln_in_b = (const float*)d_in[7];
    const float* W_gat = (const float*)d_in[8];
    const float* b_gat = (const float*)d_in[9];
    const float* W_e = (const float*)d_in[10];
    const float* a_src = (const float*)d_in[11];
    const float* a_dst = (const float*)d_in[12];
    const float* a_edge = (const float*)d_in[13];
    const float* W_out = (const float*)d_in[14];
    const float* b_out = (const float*)d_in[15];
    const float* ln_out_g = (const float*)d_in[16];
    const float* ln_out_b = (const float*)d_in[17];

    const int* src = edge_index;
    const int* dst = edge_index + NE;

    float* out = (float*)d_out;
    float* graph_out = nullptr;
    float* node_out = nullptr;
    if (out_size >= NG * HID + NN * HID) {
        graph_out = out;
        node_out = out + NG * HID;
    } else if (out_size >= NN * HID) {
        node_out = out;
    } else {
        graph_out = out;
    }

    const int EB = (NE + 255) / 256;
    const int NB = (NN + 255) / 256;
    const int NPARTS = (NN + 1023) / 1024;  // 49
    const int WS_B = (HID * HID + 255) / 256;
    dim3 gemm_grid((NN + GM - 1) / GM, HID / GN);  // (782, 2)

    // Launch order keeps layer-0 k_wmma_gemm at index 3 (ncu window).
    k_input_proj<<<NN, 256>>>(x, x_W_in, b_in, ln_in_g, ln_in_b);   // 0
    k_zero_cursor<<<NB, 256>>>();                                    // 1
    k_wsplit<<<WS_B, 256>>>(W_gat);                                  // 2 (layer 0 W)
    k_wmma_gemm<<<gemm_grid, 128>>>(0, b_gat);                       // 3 (layer 0)
    k_count_deg<<<EB, 256>>>(dst);                                   // 4
    k_scan1<<<NPARTS, 1024>>>();                                     // 5
    k_scan2<<<1, 64>>>(NPARTS);                                      // 6
    k_scan3<<<NB, 256>>>();                                          // 7
    k_scatter<<<EB, 256>>>(src, dst);                                // 8

    int cur = 0;  // 0 = bufA, 1 = bufB
    for (int l = 0; l < NLAYERS; l++) {
        int nxt = 1 - cur;
        const float* Wl = W_gat + l * HID * HID;
        const float* bl = b_gat + l * HID;
        const float* Wel = W_e + l * EDIM * HID;
        const float* asl = a_src + l * NHEADS * HD;
        const float* adl = a_dst + l * NHEADS * HD;
        const float* ael = a_edge + l * NHEADS * HD;

        if (l > 0) {
            k_wsplit<<<WS_B, 256>>>(Wl);
            k_wmma_gemm<<<gemm_grid, 128>>>(cur, bl);
        }
        k_edge_coef<<<1, 384>>>(Wel, ael);
        k_sdots<<<(NN * NHEADS + 7) / 8, 256>>>(asl, adl);
        k_edge_logits<<<EB, 256>>>(src, dst, edge_attr);
        k_node_stats<<<(NN + 7) / 8, 256>>>();
        k_aggregate<<<NN / 4, 256>>>(cur, nxt);
        cur = nxt;
    }

    // ---- output projection + LN + ELU ----
    k_wsplit<<<WS_B, 256>>>(W_out);
    k_wmma_gemm<<<gemm_grid, 128>>>(cur, b_out);
    int fsel = 1 - cur;
    k_ln_out<<<NN, 256>>>(ln_out_g, ln_out_b, node_out, fsel);

    // ---- global mean pool ----
    if (graph_out) {
        k_graph_starts<<<NB, 256>>>(batch);
        k_zero_float<<<(NG * HID + 255) / 256, 256>>>(graph_out, NG * HID);
        dim3 pg(NG, 16);
        k_pool_partial<<<pg, 256>>>(node_out, fsel, graph_out);
        k_pool_final<<<NG, 256>>>(graph_out);
    }
}

// round 14
// speedup vs baseline: 1.1639x; 1.1123x over previous
#include <cuda_runtime.h>
#include <cuda_bf16.h>
#include <mma.h>
#include <math.h>
#include <stdint.h>

using namespace nvcuda;

#define NN 50000
#define NE 800000
#define NDIM 8
#define EDIM 3
#define HID 256
#define NHEADS 4
#define HD 64
#define NLAYERS 3
#define NG 64
#define NEG_SLOPE 0.2f

// ---------------- scratch (device globals; no allocation allowed) ----------------
__device__ float g_bufA[NN * HID];
__device__ float g_bufB[NN * HID];
__device__ float g_hp[NN * HID];
__device__ float g_logit[NE * NHEADS];   // CSR-ordered leaky-relu'd logits
__device__ float g_ssrc[NN * NHEADS];
__device__ float g_sdst[NN * NHEADS];
__device__ float g_m[NN * NHEADS];
__device__ float g_invden[NN * NHEADS];
__device__ int   g_rowstart[NN + 1];
__device__ int   g_cursor[NN];
__device__ int   g_inv[NE];              // edge -> CSR position
__device__ int   g_psrc[NE];             // CSR-ordered src node ids
__device__ int   g_part[64];
__device__ float g_coef[EDIM * NHEADS];
__device__ int   g_gstart[NG + 1];
__device__ __nv_bfloat16 g_Wh[HID * HID];
__device__ __nv_bfloat16 g_Wl[HID * HID];

__device__ __forceinline__ float* selbuf(int s) { return s ? g_bufB : g_bufA; }
__device__ __forceinline__ float elu(float x) { return x > 0.f ? x : expf(x) - 1.f; }

// ---------------- W -> bf16 hi/lo split (once per layer) ----------------
__global__ void k_wsplit(const float* __restrict__ W) {
    int i = blockIdx.x * blockDim.x + threadIdx.x;
    if (i >= HID * HID) return;
    float w = W[i];
    __nv_bfloat16 h = __float2bfloat16(w);
    g_Wh[i] = h;
    g_Wl[i] = __float2bfloat16(w - __bfloat162float(h));
}

// ================= wmma bf16-split GEMM (frozen best config): g_hp = selbuf(asel) @ W + bias ===
#define GM 64
#define GN 128
#define APAD 24    // 48B stride
#define BPAD 136   // 272B stride

__global__ void __launch_bounds__(128, 3) k_wmma_gemm(int asel, const float* __restrict__ bias) {
    const float* A = selbuf(asel);
    __shared__ __nv_bfloat16 Ah[GM * APAD], Al[GM * APAD];
    __shared__ __nv_bfloat16 Bh[16 * BPAD], Bl[16 * BPAD];
    __shared__ float biasT[16 * GN];

    int tid = threadIdx.x;
    int wid = tid >> 5;
    int wm = wid >> 1;           // 0..1 -> 32-row slab
    int wn = wid & 1;            // 0..1 -> 64-col slab
    int bm = blockIdx.x * GM;
    int bn = blockIdx.y * GN;

    for (int i = tid; i < 16 * GN; i += 128) biasT[i] = bias[bn + (i & (GN - 1))];
    __syncthreads();

    wmma::fragment<wmma::accumulator, 16, 16, 16, float> acc[2][4];
#pragma unroll
    for (int i = 0; i < 2; i++)
#pragma unroll
        for (int j = 0; j < 4; j++)
            wmma::load_matrix_sync(acc[i][j], &biasT[wn * 64 + j * 16], GN, wmma::mem_row_major);

    for (int k0 = 0; k0 < HID; k0 += 16) {
        {
            int row = tid >> 1;
            int cq = (tid & 1) << 3;
            int gr = bm + row;
            float4 v0 = make_float4(0.f, 0.f, 0.f, 0.f), v1 = v0;
            if (gr < NN) {
                const float* ap = A + (size_t)gr * HID + k0 + cq;
                v0 = *(const float4*)ap;
                v1 = *(const float4*)(ap + 4);
            }
            __nv_bfloat16 hh[8], ll[8];
            float vv[8] = {v0.x, v0.y, v0.z, v0.w, v1.x, v1.y, v1.z, v1.w};
#pragma unroll
            for (int q = 0; q < 8; q++) {
                hh[q] = __float2bfloat16(vv[q]);
                ll[q] = __float2bfloat16(vv[q] - __bfloat162float(hh[q]));
            }
            *(uint4*)(Ah + row * APAD + cq) = *(uint4*)hh;
            *(uint4*)(Al + row * APAD + cq) = *(uint4*)ll;
        }
        {
            int row = tid >> 3;
            int cb = (tid & 7) << 4;
            size_t go = (size_t)(k0 + row) * HID + bn + cb;
            *(uint4*)(Bh + row * BPAD + cb) = *(const uint4*)(g_Wh + go);
            *(uint4*)(Bh + row * BPAD + cb + 8) = *(const uint4*)(g_Wh + go + 8);
            *(uint4*)(Bl + row * BPAD + cb) = *(const uint4*)(g_Wl + go);
            *(uint4*)(Bl + row * BPAD + cb + 8) = *(const uint4*)(g_Wl + go + 8);
        }
        __syncthreads();

        wmma::fragment<wmma::matrix_b, 16, 16, 16, __nv_bfloat16, wmma::row_major> fbh[4], fbl[4];
#pragma unroll
        for (int j = 0; j < 4; j++) {
            wmma::load_matrix_sync(fbh[j], &Bh[wn * 64 + j * 16], BPAD);
            wmma::load_matrix_sync(fbl[j], &Bl[wn * 64 + j * 16], BPAD);
        }
#pragma unroll
        for (int i = 0; i < 2; i++) {
            wmma::fragment<wmma::matrix_a, 16, 16, 16, __nv_bfloat16, wmma::row_major> fah, fal;
            wmma::load_matrix_sync(fah, &Ah[(wm * 32 + i * 16) * APAD], APAD);
            wmma::load_matrix_sync(fal, &Al[(wm * 32 + i * 16) * APAD], APAD);
#pragma unroll
            for (int j = 0; j < 4; j++) {
                wmma::mma_sync(acc[i][j], fah, fbh[j], acc[i][j]);
                wmma::mma_sync(acc[i][j], fal, fbh[j], acc[i][j]);
                wmma::mma_sync(acc[i][j], fah, fbl[j], acc[i][j]);
            }
        }
        __syncthreads();
    }

#pragma unroll
    for (int i = 0; i < 2; i++) {
        int gr0 = bm + wm * 32 + i * 16;
        if (gr0 < NN) {  // NN % 16 == 0
#pragma unroll
            for (int j = 0; j < 4; j++)
                wmma::store_matrix_sync(g_hp + (size_t)gr0 * HID + bn + wn * 64 + j * 16,
                                        acc[i][j], HID, wmma::mem_row_major);
        }
    }
}

// ---------------- CSR build ----------------
__global__ void k_zero_cursor() {
    int i = blockIdx.x * blockDim.x + threadIdx.x;
    if (i < NN) g_cursor[i] = 0;
}

__global__ void k_count_deg(const int* __restrict__ dst) {
    int e = blockIdx.x * blockDim.x + threadIdx.x;
    if (e < NE) atomicAdd(&g_cursor[dst[e]], 1);
}

__global__ void k_scan1() {
    __shared__ int sh[1024];
    int i = blockIdx.x * 1024 + threadIdx.x;
    int v = (i < NN) ? g_cursor[i] : 0;
    sh[threadIdx.x] = v;
    __syncthreads();
    for (int off = 1; off < 1024; off <<= 1) {
        int t = (threadIdx.x >= off) ? sh[threadIdx.x - off] : 0;
        __syncthreads();
        sh[threadIdx.x] += t;
        __syncthreads();
    }
    if (i < NN) g_rowstart[i] = sh[threadIdx.x] - v;
    if (threadIdx.x == 1023) g_part[blockIdx.x] = sh[1023];
}

__global__ void k_scan2(int nparts) {
    __shared__ int sh[64];
    int t = threadIdx.x;
    int v0 = (t < nparts) ? g_part[t] : 0;
    sh[t] = v0;
    __syncthreads();
    for (int off = 1; off < 64; off <<= 1) {
        int v = (t >= off) ? sh[t - off] : 0;
        __syncthreads();
        sh[t] += v;
        __syncthreads();
    }
    if (t < nparts) g_part[t] = sh[t] - v0;  // exclusive
}

__global__ void k_scan3() {
    int i = blockIdx.x * blockDim.x + threadIdx.x;
    if (i < NN) {
        int v = g_rowstart[i] + g_part[i >> 10];
        g_rowstart[i] = v;
        g_cursor[i] = v;
    }
    if (i == 0) g_rowstart[NN] = NE;
}

// scatter: record inverse perm and CSR-ordered src
__global__ void k_scatter(const int* __restrict__ src, const int* __restrict__ dst) {
    int e = blockIdx.x * blockDim.x + threadIdx.x;
    if (e < NE) {
        int d = dst[e];
        int pos = atomicAdd(&g_cursor[d], 1);
        g_inv[e] = pos;
        g_psrc[pos] = src[e];
    }
}

// ---------------- input projection + LN + ELU (warp-per-row) -> g_bufA ----------------
__global__ void __launch_bounds__(256) k_input_proj(const float* __restrict__ x,
                                                    const float* __restrict__ Win,
                                                    const float* __restrict__ bin,
                                                    const float* __restrict__ lg,
                                                    const float* __restrict__ lb) {
    int wid = threadIdx.x >> 5;
    int lane = threadIdx.x & 31;
    int n = blockIdx.x * 8 + wid;            // NN % 8 == 0
    if (n >= NN) return;

    float xv = (lane < NDIM) ? x[n * NDIM + lane] : 0.f;
    float xk[NDIM];
#pragma unroll
    for (int k = 0; k < NDIM; k++) xk[k] = __shfl_sync(0xffffffffu, xv, k);

    float v[8], s = 0.f, s2 = 0.f;
#pragma unroll
    for (int q = 0; q < 8; q++) {
        int c = q * 32 + lane;
        float a = bin[c];
#pragma unroll
        for (int k = 0; k < NDIM; k++) a += xk[k] * Win[k * HID + c];
        v[q] = a;
        s += a;
        s2 += a * a;
    }
#pragma unroll
    for (int off = 16; off > 0; off >>= 1) {
        s += __shfl_xor_sync(0xffffffffu, s, off);
        s2 += __shfl_xor_sync(0xffffffffu, s2, off);
    }
    float mean = s * (1.f / HID);
    float var = s2 * (1.f / HID) - mean * mean;
    float rs = rsqrtf(var + 1e-5f);
#pragma unroll
    for (int q = 0; q < 8; q++) {
        int c = q * 32 + lane;
        float y = (v[q] - mean) * rs * lg[c] + lb[c];
        g_bufA[(size_t)n * HID + c] = elu(y);
    }
}

// ---------------- per-(node,head) attention dots on g_hp (+fused edge_coef in last block) -----
__global__ void k_sdots(const float* __restrict__ a_s, const float* __restrict__ a_d,
                        const float* __restrict__ We, const float* __restrict__ ae) {
    int lane = threadIdx.x & 31;
    if (blockIdx.x == gridDim.x - 1) {
        // 12 tiny dots: coef[k,h] = dot(We[k, h*64:...], ae[h,:])
        int wd = threadIdx.x >> 5;  // 8 warps
        for (int d = wd; d < EDIM * NHEADS; d += 8) {
            int k = d >> 2, h = d & 3;
            const float* wrow = We + k * HID + h * HD;
            const float* arow = ae + h * HD;
            float v = wrow[lane] * arow[lane] + wrow[lane + 32] * arow[lane + 32];
#pragma unroll
            for (int off = 16; off > 0; off >>= 1) v += __shfl_down_sync(0xffffffffu, v, off);
            if (lane == 0) g_coef[k * NHEADS + h] = v;
        }
        return;
    }
    int w = (blockIdx.x * blockDim.x + threadIdx.x) >> 5;
    if (w >= NN * NHEADS) return;
    int n = w >> 2, h = w & 3;
    const float* row = g_hp + (size_t)n * HID + h * HD;
    float r0 = row[lane], r1 = row[lane + 32];
    float v1 = r0 * a_s[h * HD + lane] + r1 * a_s[h * HD + lane + 32];
    float v2 = r0 * a_d[h * HD + lane] + r1 * a_d[h * HD + lane + 32];
#pragma unroll
    for (int off = 16; off > 0; off >>= 1) {
        v1 += __shfl_down_sync(0xffffffffu, v1, off);
        v2 += __shfl_down_sync(0xffffffffu, v2, off);
    }
    if (lane == 0) { g_ssrc[w] = v1; g_sdst[w] = v2; }
}

// ---------------- edge logits -> CSR-ordered slots (coalesced reads, scattered store) ----------
__global__ void k_edge_logits(const int* __restrict__ src, const int* __restrict__ dst,
                              const float* __restrict__ ea) {
    int e = blockIdx.x * blockDim.x + threadIdx.x;
    if (e >= NE) return;
    int s = src[e], d = dst[e];
    int pos = g_inv[e];
    float a0 = ea[e * 3 + 0], a1 = ea[e * 3 + 1], a2 = ea[e * 3 + 2];
    float4 sv = *(const float4*)&g_ssrc[s * NHEADS];
    float4 dv = *(const float4*)&g_sdst[d * NHEADS];
    float4 out;
    float* o = (float*)&out;
    const float* ss = (const float*)&sv;
    const float* dd = (const float*)&dv;
#pragma unroll
    for (int h = 0; h < NHEADS; h++) {
        float lg = ss[h] + dd[h] +
                   a0 * g_coef[0 * NHEADS + h] + a1 * g_coef[1 * NHEADS + h] +
                   a2 * g_coef[2 * NHEADS + h];
        o[h] = lg > 0.f ? lg : NEG_SLOPE * lg;
    }
    *(float4*)&g_logit[(size_t)pos * NHEADS] = out;
}

// ---------------- per-node softmax stats: warp-per-node, ONLINE single pass ----------------
__device__ __forceinline__ void online_merge(float& m, float& d, float m2, float d2) {
    float mn = fmaxf(m, m2);
    d = d * expf(m - mn) + d2 * expf(m2 - mn);
    m = mn;
}

__global__ void k_node_stats() {
    int w = (blockIdx.x * blockDim.x + threadIdx.x) >> 5;
    int lane = threadIdx.x & 31;
    if (w >= NN) return;
    int s0 = g_rowstart[w], s1 = g_rowstart[w + 1];

    float m0 = -3.4e38f, m1 = -3.4e38f, m2 = -3.4e38f, m3 = -3.4e38f;
    float d0 = 0.f, d1 = 0.f, d2 = 0.f, d3 = 0.f;
    for (int j = s0 + lane; j < s1; j += 32) {
        float4 lg = *(const float4*)&g_logit[(size_t)j * NHEADS];
        online_merge(m0, d0, lg.x, 1.f);
        online_merge(m1, d1, lg.y, 1.f);
        online_merge(m2, d2, lg.z, 1.f);
        online_merge(m3, d3, lg.w, 1.f);
    }
#pragma unroll
    for (int off = 16; off > 0; off >>= 1) {
        online_merge(m0, d0, __shfl_xor_sync(0xffffffffu, m0, off), __shfl_xor_sync(0xffffffffu, d0, off));
        online_merge(m1, d1, __shfl_xor_sync(0xffffffffu, m1, off), __shfl_xor_sync(0xffffffffu, d1, off));
        online_merge(m2, d2, __shfl_xor_sync(0xffffffffu, m2, off), __shfl_xor_sync(0xffffffffu, d2, off));
        online_merge(m3, d3, __shfl_xor_sync(0xffffffffu, m3, off), __shfl_xor_sync(0xffffffffu, d3, off));
    }
    if (lane == 0) {
        if (s0 == s1) { m0 = m1 = m2 = m3 = 0.f; }
        float4 mv = make_float4(m0, m1, m2, m3);
        *(float4*)&g_m[w * NHEADS] = mv;
        float4 inv;
        inv.x = 1.f / fmaxf(d0, 1e-16f);
        inv.y = 1.f / fmaxf(d1, 1e-16f);
        inv.z = 1.f / fmaxf(d2, 1e-16f);
        inv.w = 1.f / fmaxf(d3, 1e-16f);
        *(float4*)&g_invden[w * NHEADS] = inv;
    }
}

// ---------------- staged aggregation: contiguous psrc/logit streams, random hp gathers ----------
#define ECH 64
__global__ void __launch_bounds__(256) k_aggregate(int insel, int outsel) {
    const float* hin = selbuf(insel);
    float* hout = selbuf(outsel);
    __shared__ int s_src[4][ECH];
    __shared__ float s_al[4][ECH * 4];
    __shared__ int s_deg[4];

    int tid = threadIdx.x;
    int slot = tid >> 6;
    int lt = tid & 63;
    int n = blockIdx.x * 4 + slot;   // NN % 4 == 0

    int s0 = g_rowstart[n], s1 = g_rowstart[n + 1];
    int deg = s1 - s0;
    if (lt == 0) s_deg[slot] = deg;
    float4 m4 = *(const float4*)&g_m[n * NHEADS];
    float4 iv4 = *(const float4*)&g_invden[n * NHEADS];
    __syncthreads();
    int maxdeg = max(max(s_deg[0], s_deg[1]), max(s_deg[2], s_deg[3]));

    int h = lt >> 4;                 // head for cols [lt*4, lt*4+4)
    float4 acc = make_float4(0.f, 0.f, 0.f, 0.f);

    for (int base = 0; base < maxdeg; base += ECH) {
        int cnt = min(ECH, deg - base);
        if (lt < cnt) {
            int j = s0 + base + lt;
            s_src[slot][lt] = g_psrc[j];
            float4 lg = *(const float4*)&g_logit[(size_t)j * NHEADS];
            float4 a;
            a.x = expf(lg.x - m4.x) * iv4.x;
            a.y = expf(lg.y - m4.y) * iv4.y;
            a.z = expf(lg.z - m4.z) * iv4.z;
            a.w = expf(lg.w - m4.w) * iv4.w;
            *(float4*)&s_al[slot][lt * 4] = a;
        }
        __syncthreads();
#pragma unroll 4
        for (int j = 0; j < cnt; j++) {
            int s = s_src[slot][j];
            float a = s_al[slot][j * 4 + h];
            float4 hv = *(const float4*)&g_hp[(size_t)s * HID + lt * 4];
            acc.x += a * hv.x; acc.y += a * hv.y;
            acc.z += a * hv.z; acc.w += a * hv.w;
        }
        __syncthreads();
    }

    float4 r = *(const float4*)&hin[(size_t)n * HID + lt * 4];
    float4 o;
    o.x = elu(acc.x + r.x); o.y = elu(acc.y + r.y);
    o.z = elu(acc.z + r.z); o.w = elu(acc.w + r.w);
    *(float4*)&hout[(size_t)n * HID + lt * 4] = o;
}

// ---------------- output LN + ELU (warp-per-row), write node_emb ----------------
__global__ void __launch_bounds__(256) k_ln_out(const float* __restrict__ lg,
                                                const float* __restrict__ lb,
                                                float* __restrict__ outp, int fallback_sel) {
    float* o = outp ? outp : selbuf(fallback_sel);
    int wid = threadIdx.x >> 5;
    int lane = threadIdx.x & 31;
    int n = blockIdx.x * 8 + wid;            // NN % 8 == 0
    if (n >= NN) return;

    float4 a = *(const float4*)&g_hp[(size_t)n * HID + lane * 4];
    float4 b = *(const float4*)&g_hp[(size_t)n * HID + 128 + lane * 4];
    float s = a.x + a.y + a.z + a.w + b.x + b.y + b.z + b.w;
    float s2 = a.x * a.x + a.y * a.y + a.z * a.z + a.w * a.w +
               b.x * b.x + b.y * b.y + b.z * b.z + b.w * b.w;
#pragma unroll
    for (int off = 16; off > 0; off >>= 1) {
        s += __shfl_xor_sync(0xffffffffu, s, off);
        s2 += __shfl_xor_sync(0xffffffffu, s2, off);
    }
    float mean = s * (1.f / HID);
    float var = s2 * (1.f / HID) - mean * mean;
    float rs = rsqrtf(var + 1e-5f);

    float4 g0 = *(const float4*)&lg[lane * 4];
    float4 g1 = *(const float4*)&lg[128 + lane * 4];
    float4 b0 = *(const float4*)&lb[lane * 4];
    float4 b1 = *(const float4*)&lb[128 + lane * 4];
    float4 o0, o1;
    o0.x = elu((a.x - mean) * rs * g0.x + b0.x);
    o0.y = elu((a.y - mean) * rs * g0.y + b0.y);
    o0.z = elu((a.z - mean) * rs * g0.z + b0.z);
    o0.w = elu((a.w - mean) * rs * g0.w + b0.w);
    o1.x = elu((b.x - mean) * rs * g1.x + b1.x);
    o1.y = elu((b.y - mean) * rs * g1.y + b1.y);
    o1.z = elu((b.z - mean) * rs * g1.z + b1.z);
    o1.w = elu((b.w - mean) * rs * g1.w + b1.w);
    *(float4*)&o[(size_t)n * HID + lane * 4] = o0;
    *(float4*)&o[(size_t)n * HID + 128 + lane * 4] = o1;
}

// ---------------- pooling ----------------
__global__ void k_graph_starts(const int* __restrict__ batch) {
    int n = blockIdx.x * blockDim.x + threadIdx.x;
    if (n >= NN) return;
    int b = batch[n];
    int bp = (n == 0) ? -1 : batch[n - 1];
    for (int g = bp + 1; g <= b; g++) g_gstart[g] = n;
    if (n == NN - 1)
        for (int g = b + 1; g <= NG; g++) g_gstart[g] = NN;
}

__global__ void k_zero_float(float* p, int n) {
    int i = blockIdx.x * blockDim.x + threadIdx.x;
    if (i < n) p[i] = 0.f;
}

__global__ void k_pool_partial(const float* __restrict__ embp, int fallback_sel,
                               float* __restrict__ out) {
    const float* emb = embp ? embp : selbuf(fallback_sel);
    int g = blockIdx.x;
    int part = blockIdx.y;
    int c = threadIdx.x;
    int s = g_gstart[g], e = g_gstart[g + 1];
    int cnt = e - s;
    if (cnt <= 0) return;
    int chunk = (cnt + gridDim.y - 1) / gridDim.y;
    int ps = s + part * chunk;
    int pe = min(ps + chunk, e);
    if (ps >= pe) return;
    float acc = 0.f;
    for (int n = ps; n < pe; n++) acc += emb[n * HID + c];
    atomicAdd(&out[g * HID + c], acc);
}

__global__ void k_pool_final(float* __restrict__ out) {
    int g = blockIdx.x;
    int c = threadIdx.x;
    float cnt = (float)(g_gstart[g + 1] - g_gstart[g]);
    out[g * HID + c] /= fmaxf(cnt, 1.f);
}

// ---------------- launch ----------------
extern "C" void kernel_launch(void* const* d_in, const int* in_sizes, int n_in,
                              void* d_out, int out_size) {
    const float* x = (const float*)d_in[0];
    const int* edge_index = (const int*)d_in[1];   // int32
    const float* edge_attr = (const float*)d_in[2];
    const int* batch = (const int*)d_in[3];        // int32
    const float* x_W_in = (const float*)d_in[4];
    const float* b_in = (const float*)d_in[5];
    const float* ln_in_g = (const float*)d_in[6];
    const float* ln_in_b = (const float*)d_in[7];
    const float* W_gat = (const float*)d_in[8];
    const float* b_gat = (const float*)d_in[9];
    const float* W_e = (const float*)d_in[10];
    const float* a_src = (const float*)d_in[11];
    const float* a_dst = (const float*)d_in[12];
    const float* a_edge = (const float*)d_in[13];
    const float* W_out = (const float*)d_in[14];
    const float* b_out = (const float*)d_in[15];
    const float* ln_out_g = (const float*)d_in[16];
    const float* ln_out_b = (const float*)d_in[17];

    const int* src = edge_index;
    const int* dst = edge_index + NE;

    float* out = (float*)d_out;
    float* graph_out = nullptr;
    float* node_out = nullptr;
    if (out_size >= NG * HID + NN * HID) {
        graph_out = out;
        node_out = out + NG * HID;
    } else if (out_size >= NN * HID) {
        node_out = out;
    } else {
        graph_out = out;
    }

    const int EB = (NE + 255) / 256;
    const int NB = (NN + 255) / 256;
    const int NPARTS = (NN + 1023) / 1024;  // 49
    const int WS_B = (HID * HID + 255) / 256;
    const int SD_B = (NN * NHEADS + 7) / 8 + 1;  // +1: fused edge_coef block
    dim3 gemm_grid((NN + GM - 1) / GM, HID / GN);  // (782, 2)

    // Launch order keeps layer-0 k_wmma_gemm at index 3 (ncu window).
    k_input_proj<<<NN / 8, 256>>>(x, x_W_in, b_in, ln_in_g, ln_in_b); // 0
    k_zero_cursor<<<NB, 256>>>();                                    // 1
    k_wsplit<<<WS_B, 256>>>(W_gat);                                  // 2 (layer 0 W)
    k_wmma_gemm<<<gemm_grid, 128>>>(0, b_gat);                       // 3 (layer 0)
    k_count_deg<<<EB, 256>>>(dst);                                   // 4
    k_scan1<<<NPARTS, 1024>>>();                                     // 5
    k_scan2<<<1, 64>>>(NPARTS);                                      // 6
    k_scan3<<<NB, 256>>>();                                          // 7
    k_scatter<<<EB, 256>>>(src, dst);                                // 8

    int cur = 0;  // 0 = bufA, 1 = bufB
    for (int l = 0; l < NLAYERS; l++) {
        int nxt = 1 - cur;
        const float* Wl = W_gat + l * HID * HID;
        const float* bl = b_gat + l * HID;
        const float* Wel = W_e + l * EDIM * HID;
        const float* asl = a_src + l * NHEADS * HD;
        const float* adl = a_dst + l * NHEADS * HD;
        const float* ael = a_edge + l * NHEADS * HD;

        if (l > 0) {
            k_wsplit<<<WS_B, 256>>>(Wl);
            k_wmma_gemm<<<gemm_grid, 128>>>(cur, bl);
        }
        k_sdots<<<SD_B, 256>>>(asl, adl, Wel, ael);
        k_edge_logits<<<EB, 256>>>(src, dst, edge_attr);
        k_node_stats<<<(NN + 7) / 8, 256>>>();
        k_aggregate<<<NN / 4, 256>>>(cur, nxt);
        cur = nxt;
    }

    // ---- output projection + LN + ELU ----
    k_wsplit<<<WS_B, 256>>>(W_out);
    k_wmma_gemm<<<gemm_grid, 128>>>(cur, b_out);
    int fsel = 1 - cur;
    k_ln_out<<<NN / 8, 256>>>(ln_out_g, ln_out_b, node_out, fsel);

    // ---- global mean pool ----
    if (graph_out) {
        k_graph_starts<<<NB, 256>>>(batch);
        k_zero_float<<<(NG * HID + 255) / 256, 256>>>(graph_out, NG * HID);
        dim3 pg(NG, 16);
        k_pool_partial<<<pg, 256>>>(node_out, fsel, graph_out);
        k_pool_final<<<NG, 256>>>(graph_out);
    }
}

// round 15
// speedup vs baseline: 1.1903x; 1.0227x over previous
#include <cuda_runtime.h>
#include <cuda_bf16.h>
#include <mma.h>
#include <math.h>
#include <stdint.h>

using namespace nvcuda;

#define NN 50000
#define NE 800000
#define NDIM 8
#define EDIM 3
#define HID 256
#define NHEADS 4
#define HD 64
#define NLAYERS 3
#define NG 64
#define NEG_SLOPE 0.2f

// ---------------- scratch (device globals; no allocation allowed) ----------------
__device__ float g_bufA[NN * HID];
__device__ float g_bufB[NN * HID];
__device__ float g_hp[NN * HID];
__device__ float g_logit[NE * NHEADS];   // CSR-ordered leaky-relu'd logits
__device__ float g_ssrc[NN * NHEADS];
__device__ float g_sdst[NN * NHEADS];
__device__ float g_m[NN * NHEADS];
__device__ float g_invden[NN * NHEADS];
__device__ int   g_rowstart[NN + 1];
__device__ int   g_cursor[NN];
__device__ int   g_psrc[NE];             // CSR-ordered src node ids
__device__ float g_pea[NE * 4];          // CSR-ordered edge_attr (padded to float4)
__device__ int   g_part[64];
__device__ float g_coef[EDIM * NHEADS];
__device__ int   g_gstart[NG + 1];
__device__ __nv_bfloat16 g_Wh[HID * HID];
__device__ __nv_bfloat16 g_Wl[HID * HID];

__device__ __forceinline__ float* selbuf(int s) { return s ? g_bufB : g_bufA; }
__device__ __forceinline__ float elu(float x) { return x > 0.f ? x : expf(x) - 1.f; }

// ---------------- W -> bf16 hi/lo split (once per layer) ----------------
__global__ void k_wsplit(const float* __restrict__ W) {
    int i = blockIdx.x * blockDim.x + threadIdx.x;
    if (i >= HID * HID) return;
    float w = W[i];
    __nv_bfloat16 h = __float2bfloat16(w);
    g_Wh[i] = h;
    g_Wl[i] = __float2bfloat16(w - __bfloat162float(h));
}

// ================= wmma bf16-split GEMM (frozen best config): g_hp = selbuf(asel) @ W + bias ===
#define GM 64
#define GN 128
#define APAD 24    // 48B stride
#define BPAD 136   // 272B stride

__global__ void __launch_bounds__(128, 3) k_wmma_gemm(int asel, const float* __restrict__ bias) {
    const float* A = selbuf(asel);
    __shared__ __nv_bfloat16 Ah[GM * APAD], Al[GM * APAD];
    __shared__ __nv_bfloat16 Bh[16 * BPAD], Bl[16 * BPAD];
    __shared__ float biasT[16 * GN];

    int tid = threadIdx.x;
    int wid = tid >> 5;
    int wm = wid >> 1;           // 0..1 -> 32-row slab
    int wn = wid & 1;            // 0..1 -> 64-col slab
    int bm = blockIdx.x * GM;
    int bn = blockIdx.y * GN;

    for (int i = tid; i < 16 * GN; i += 128) biasT[i] = bias[bn + (i & (GN - 1))];
    __syncthreads();

    wmma::fragment<wmma::accumulator, 16, 16, 16, float> acc[2][4];
#pragma unroll
    for (int i = 0; i < 2; i++)
#pragma unroll
        for (int j = 0; j < 4; j++)
            wmma::load_matrix_sync(acc[i][j], &biasT[wn * 64 + j * 16], GN, wmma::mem_row_major);

    for (int k0 = 0; k0 < HID; k0 += 16) {
        {
            int row = tid >> 1;
            int cq = (tid & 1) << 3;
            int gr = bm + row;
            float4 v0 = make_float4(0.f, 0.f, 0.f, 0.f), v1 = v0;
            if (gr < NN) {
                const float* ap = A + (size_t)gr * HID + k0 + cq;
                v0 = *(const float4*)ap;
                v1 = *(const float4*)(ap + 4);
            }
            __nv_bfloat16 hh[8], ll[8];
            float vv[8] = {v0.x, v0.y, v0.z, v0.w, v1.x, v1.y, v1.z, v1.w};
#pragma unroll
            for (int q = 0; q < 8; q++) {
                hh[q] = __float2bfloat16(vv[q]);
                ll[q] = __float2bfloat16(vv[q] - __bfloat162float(hh[q]));
            }
            *(uint4*)(Ah + row * APAD + cq) = *(uint4*)hh;
            *(uint4*)(Al + row * APAD + cq) = *(uint4*)ll;
        }
        {
            int row = tid >> 3;
            int cb = (tid & 7) << 4;
            size_t go = (size_t)(k0 + row) * HID + bn + cb;
            *(uint4*)(Bh + row * BPAD + cb) = *(const uint4*)(g_Wh + go);
            *(uint4*)(Bh + row * BPAD + cb + 8) = *(const uint4*)(g_Wh + go + 8);
            *(uint4*)(Bl + row * BPAD + cb) = *(const uint4*)(g_Wl + go);
            *(uint4*)(Bl + row * BPAD + cb + 8) = *(const uint4*)(g_Wl + go + 8);
        }
        __syncthreads();

        wmma::fragment<wmma::matrix_b, 16, 16, 16, __nv_bfloat16, wmma::row_major> fbh[4], fbl[4];
#pragma unroll
        for (int j = 0; j < 4; j++) {
            wmma::load_matrix_sync(fbh[j], &Bh[wn * 64 + j * 16], BPAD);
            wmma::load_matrix_sync(fbl[j], &Bl[wn * 64 + j * 16], BPAD);
        }
#pragma unroll
        for (int i = 0; i < 2; i++) {
            wmma::fragment<wmma::matrix_a, 16, 16, 16, __nv_bfloat16, wmma::row_major> fah, fal;
            wmma::load_matrix_sync(fah, &Ah[(wm * 32 + i * 16) * APAD], APAD);
            wmma::load_matrix_sync(fal, &Al[(wm * 32 + i * 16) * APAD], APAD);
#pragma unroll
            for (int j = 0; j < 4; j++) {
                wmma::mma_sync(acc[i][j], fah, fbh[j], acc[i][j]);
                wmma::mma_sync(acc[i][j], fal, fbh[j], acc[i][j]);
                wmma::mma_sync(acc[i][j], fah, fbl[j], acc[i][j]);
            }
        }
        __syncthreads();
    }

#pragma unroll
    for (int i = 0; i < 2; i++) {
        int gr0 = bm + wm * 32 + i * 16;
        if (gr0 < NN) {  // NN % 16 == 0
#pragma unroll
            for (int j = 0; j < 4; j++)
                wmma::store_matrix_sync(g_hp + (size_t)gr0 * HID + bn + wn * 64 + j * 16,
                                        acc[i][j], HID, wmma::mem_row_major);
        }
    }
}

// ---------------- CSR build ----------------
__global__ void k_zero_cursor() {
    int i = blockIdx.x * blockDim.x + threadIdx.x;
    if (i < NN) g_cursor[i] = 0;
}

__global__ void k_count_deg(const int* __restrict__ dst) {
    int e = blockIdx.x * blockDim.x + threadIdx.x;
    if (e < NE) atomicAdd(&g_cursor[dst[e]], 1);
}

__global__ void k_scan1() {
    __shared__ int sh[1024];
    int i = blockIdx.x * 1024 + threadIdx.x;
    int v = (i < NN) ? g_cursor[i] : 0;
    sh[threadIdx.x] = v;
    __syncthreads();
    for (int off = 1; off < 1024; off <<= 1) {
        int t = (threadIdx.x >= off) ? sh[threadIdx.x - off] : 0;
        __syncthreads();
        sh[threadIdx.x] += t;
        __syncthreads();
    }
    if (i < NN) g_rowstart[i] = sh[threadIdx.x] - v;
    if (threadIdx.x == 1023) g_part[blockIdx.x] = sh[1023];
}

__global__ void k_scan2(int nparts) {
    __shared__ int sh[64];
    int t = threadIdx.x;
    int v0 = (t < nparts) ? g_part[t] : 0;
    sh[t] = v0;
    __syncthreads();
    for (int off = 1; off < 64; off <<= 1) {
        int v = (t >= off) ? sh[t - off] : 0;
        __syncthreads();
        sh[t] += v;
        __syncthreads();
    }
    if (t < nparts) g_part[t] = sh[t] - v0;  // exclusive
}

__global__ void k_scan3() {
    int i = blockIdx.x * blockDim.x + threadIdx.x;
    if (i < NN) {
        int v = g_rowstart[i] + g_part[i >> 10];
        g_rowstart[i] = v;
        g_cursor[i] = v;
    }
    if (i == 0) g_rowstart[NN] = NE;
}

// scatter: CSR-ordered src ids + CSR-ordered edge_attr (float4-padded)
__global__ void k_scatter(const int* __restrict__ src, const int* __restrict__ dst,
                          const float* __restrict__ ea) {
    int e = blockIdx.x * blockDim.x + threadIdx.x;
    if (e < NE) {
        int d = dst[e];
        int pos = atomicAdd(&g_cursor[d], 1);
        g_psrc[pos] = src[e];
        float4 v;
        v.x = ea[e * 3 + 0];
        v.y = ea[e * 3 + 1];
        v.z = ea[e * 3 + 2];
        v.w = 0.f;
        *(float4*)&g_pea[(size_t)pos * 4] = v;
    }
}

// ---------------- input projection + LN + ELU (warp-per-row) -> g_bufA ----------------
__global__ void __launch_bounds__(256) k_input_proj(const float* __restrict__ x,
                                                    const float* __restrict__ Win,
                                                    const float* __restrict__ bin,
                                                    const float* __restrict__ lg,
                                                    const float* __restrict__ lb) {
    int wid = threadIdx.x >> 5;
    int lane = threadIdx.x & 31;
    int n = blockIdx.x * 8 + wid;            // NN % 8 == 0
    if (n >= NN) return;

    float xv = (lane < NDIM) ? x[n * NDIM + lane] : 0.f;
    float xk[NDIM];
#pragma unroll
    for (int k = 0; k < NDIM; k++) xk[k] = __shfl_sync(0xffffffffu, xv, k);

    float v[8], s = 0.f, s2 = 0.f;
#pragma unroll
    for (int q = 0; q < 8; q++) {
        int c = q * 32 + lane;
        float a = bin[c];
#pragma unroll
        for (int k = 0; k < NDIM; k++) a += xk[k] * Win[k * HID + c];
        v[q] = a;
        s += a;
        s2 += a * a;
    }
#pragma unroll
    for (int off = 16; off > 0; off >>= 1) {
        s += __shfl_xor_sync(0xffffffffu, s, off);
        s2 += __shfl_xor_sync(0xffffffffu, s2, off);
    }
    float mean = s * (1.f / HID);
    float var = s2 * (1.f / HID) - mean * mean;
    float rs = rsqrtf(var + 1e-5f);
#pragma unroll
    for (int q = 0; q < 8; q++) {
        int c = q * 32 + lane;
        float y = (v[q] - mean) * rs * lg[c] + lb[c];
        g_bufA[(size_t)n * HID + c] = elu(y);
    }
}

// ---------------- per-(node,head) attention dots on g_hp (+fused edge_coef in last block) -----
__global__ void k_sdots(const float* __restrict__ a_s, const float* __restrict__ a_d,
                        const float* __restrict__ We, const float* __restrict__ ae) {
    int lane = threadIdx.x & 31;
    if (blockIdx.x == gridDim.x - 1) {
        int wd = threadIdx.x >> 5;  // 8 warps
        for (int d = wd; d < EDIM * NHEADS; d += 8) {
            int k = d >> 2, h = d & 3;
            const float* wrow = We + k * HID + h * HD;
            const float* arow = ae + h * HD;
            float v = wrow[lane] * arow[lane] + wrow[lane + 32] * arow[lane + 32];
#pragma unroll
            for (int off = 16; off > 0; off >>= 1) v += __shfl_down_sync(0xffffffffu, v, off);
            if (lane == 0) g_coef[k * NHEADS + h] = v;
        }
        return;
    }
    int w = (blockIdx.x * blockDim.x + threadIdx.x) >> 5;
    if (w >= NN * NHEADS) return;
    int n = w >> 2, h = w & 3;
    const float* row = g_hp + (size_t)n * HID + h * HD;
    float r0 = row[lane], r1 = row[lane + 32];
    float v1 = r0 * a_s[h * HD + lane] + r1 * a_s[h * HD + lane + 32];
    float v2 = r0 * a_d[h * HD + lane] + r1 * a_d[h * HD + lane + 32];
#pragma unroll
    for (int off = 16; off > 0; off >>= 1) {
        v1 += __shfl_down_sync(0xffffffffu, v1, off);
        v2 += __shfl_down_sync(0xffffffffu, v2, off);
    }
    if (lane == 0) { g_ssrc[w] = v1; g_sdst[w] = v2; }
}

// ---------------- FUSED: edge logits (CSR streams) + online softmax stats, warp-per-node ------
__device__ __forceinline__ void online_merge(float& m, float& d, float m2, float d2) {
    float mn = fmaxf(m, m2);
    d = d * expf(m - mn) + d2 * expf(m2 - mn);
    m = mn;
}

__global__ void k_logit_stats() {
    int w = (blockIdx.x * blockDim.x + threadIdx.x) >> 5;
    int lane = threadIdx.x & 31;
    if (w >= NN) return;
    int s0 = g_rowstart[w], s1 = g_rowstart[w + 1];

    // broadcast per-node dst-dot and layer coef
    float4 dv = *(const float4*)&g_sdst[w * NHEADS];
    float c00 = g_coef[0], c01 = g_coef[1], c02 = g_coef[2], c03 = g_coef[3];
    float c10 = g_coef[4], c11 = g_coef[5], c12 = g_coef[6], c13 = g_coef[7];
    float c20 = g_coef[8], c21 = g_coef[9], c22 = g_coef[10], c23 = g_coef[11];

    float m0 = -3.4e38f, m1 = -3.4e38f, m2 = -3.4e38f, m3 = -3.4e38f;
    float d0 = 0.f, d1 = 0.f, d2 = 0.f, d3 = 0.f;
    for (int j = s0 + lane; j < s1; j += 32) {
        int s = g_psrc[j];                                   // contiguous
        float4 a = *(const float4*)&g_pea[(size_t)j * 4];    // contiguous
        float4 sv = *(const float4*)&g_ssrc[s * NHEADS];     // random (unavoidable)
        float4 lg;
        lg.x = sv.x + dv.x + a.x * c00 + a.y * c10 + a.z * c20;
        lg.y = sv.y + dv.y + a.x * c01 + a.y * c11 + a.z * c21;
        lg.z = sv.z + dv.z + a.x * c02 + a.y * c12 + a.z * c22;
        lg.w = sv.w + dv.w + a.x * c03 + a.y * c13 + a.z * c23;
        lg.x = lg.x > 0.f ? lg.x : NEG_SLOPE * lg.x;
        lg.y = lg.y > 0.f ? lg.y : NEG_SLOPE * lg.y;
        lg.z = lg.z > 0.f ? lg.z : NEG_SLOPE * lg.z;
        lg.w = lg.w > 0.f ? lg.w : NEG_SLOPE * lg.w;
        *(float4*)&g_logit[(size_t)j * NHEADS] = lg;         // contiguous
        online_merge(m0, d0, lg.x, 1.f);
        online_merge(m1, d1, lg.y, 1.f);
        online_merge(m2, d2, lg.z, 1.f);
        online_merge(m3, d3, lg.w, 1.f);
    }
#pragma unroll
    for (int off = 16; off > 0; off >>= 1) {
        online_merge(m0, d0, __shfl_xor_sync(0xffffffffu, m0, off), __shfl_xor_sync(0xffffffffu, d0, off));
        online_merge(m1, d1, __shfl_xor_sync(0xffffffffu, m1, off), __shfl_xor_sync(0xffffffffu, d1, off));
        online_merge(m2, d2, __shfl_xor_sync(0xffffffffu, m2, off), __shfl_xor_sync(0xffffffffu, d2, off));
        online_merge(m3, d3, __shfl_xor_sync(0xffffffffu, m3, off), __shfl_xor_sync(0xffffffffu, d3, off));
    }
    if (lane == 0) {
        if (s0 == s1) { m0 = m1 = m2 = m3 = 0.f; }
        *(float4*)&g_m[w * NHEADS] = make_float4(m0, m1, m2, m3);
        float4 inv;
        inv.x = 1.f / fmaxf(d0, 1e-16f);
        inv.y = 1.f / fmaxf(d1, 1e-16f);
        inv.z = 1.f / fmaxf(d2, 1e-16f);
        inv.w = 1.f / fmaxf(d3, 1e-16f);
        *(float4*)&g_invden[w * NHEADS] = inv;
    }
}

// ---------------- staged aggregation: contiguous psrc/logit streams, random hp gathers ----------
#define ECH 64
__global__ void __launch_bounds__(256) k_aggregate(int insel, int outsel) {
    const float* hin = selbuf(insel);
    float* hout = selbuf(outsel);
    __shared__ int s_src[4][ECH];
    __shared__ float s_al[4][ECH * 4];
    __shared__ int s_deg[4];

    int tid = threadIdx.x;
    int slot = tid >> 6;
    int lt = tid & 63;
    int n = blockIdx.x * 4 + slot;   // NN % 4 == 0

    int s0 = g_rowstart[n], s1 = g_rowstart[n + 1];
    int deg = s1 - s0;
    if (lt == 0) s_deg[slot] = deg;
    float4 m4 = *(const float4*)&g_m[n * NHEADS];
    float4 iv4 = *(const float4*)&g_invden[n * NHEADS];
    __syncthreads();
    int maxdeg = max(max(s_deg[0], s_deg[1]), max(s_deg[2], s_deg[3]));

    int h = lt >> 4;                 // head for cols [lt*4, lt*4+4)
    float4 acc = make_float4(0.f, 0.f, 0.f, 0.f);

    for (int base = 0; base < maxdeg; base += ECH) {
        int cnt = min(ECH, deg - base);
        if (lt < cnt) {
            int j = s0 + base + lt;
            s_src[slot][lt] = g_psrc[j];
            float4 lg = *(const float4*)&g_logit[(size_t)j * NHEADS];
            float4 a;
            a.x = expf(lg.x - m4.x) * iv4.x;
            a.y = expf(lg.y - m4.y) * iv4.y;
            a.z = expf(lg.z - m4.z) * iv4.z;
            a.w = expf(lg.w - m4.w) * iv4.w;
            *(float4*)&s_al[slot][lt * 4] = a;
        }
        __syncthreads();
#pragma unroll 4
        for (int j = 0; j < cnt; j++) {
            int s = s_src[slot][j];
            float a = s_al[slot][j * 4 + h];
            float4 hv = *(const float4*)&g_hp[(size_t)s * HID + lt * 4];
            acc.x += a * hv.x; acc.y += a * hv.y;
            acc.z += a * hv.z; acc.w += a * hv.w;
        }
        __syncthreads();
    }

    float4 r = *(const float4*)&hin[(size_t)n * HID + lt * 4];
    float4 o;
    o.x = elu(acc.x + r.x); o.y = elu(acc.y + r.y);
    o.z = elu(acc.z + r.z); o.w = elu(acc.w + r.w);
    *(float4*)&hout[(size_t)n * HID + lt * 4] = o;
}

// ---------------- output LN + ELU (warp-per-row), write node_emb ----------------
__global__ void __launch_bounds__(256) k_ln_out(const float* __restrict__ lg,
                                                const float* __restrict__ lb,
                                                float* __restrict__ outp, int fallback_sel) {
    float* o = outp ? outp : selbuf(fallback_sel);
    int wid = threadIdx.x >> 5;
    int lane = threadIdx.x & 31;
    int n = blockIdx.x * 8 + wid;            // NN % 8 == 0
    if (n >= NN) return;

    float4 a = *(const float4*)&g_hp[(size_t)n * HID + lane * 4];
    float4 b = *(const float4*)&g_hp[(size_t)n * HID + 128 + lane * 4];
    float s = a.x + a.y + a.z + a.w + b.x + b.y + b.z + b.w;
    float s2 = a.x * a.x + a.y * a.y + a.z * a.z + a.w * a.w +
               b.x * b.x + b.y * b.y + b.z * b.z + b.w * b.w;
#pragma unroll
    for (int off = 16; off > 0; off >>= 1) {
        s += __shfl_xor_sync(0xffffffffu, s, off);
        s2 += __shfl_xor_sync(0xffffffffu, s2, off);
    }
    float mean = s * (1.f / HID);
    float var = s2 * (1.f / HID) - mean * mean;
    float rs = rsqrtf(var + 1e-5f);

    float4 g0 = *(const float4*)&lg[lane * 4];
    float4 g1 = *(const float4*)&lg[128 + lane * 4];
    float4 b0 = *(const float4*)&lb[lane * 4];
    float4 b1 = *(const float4*)&lb[128 + lane * 4];
    float4 o0, o1;
    o0.x = elu((a.x - mean) * rs * g0.x + b0.x);
    o0.y = elu((a.y - mean) * rs * g0.y + b0.y);
    o0.z = elu((a.z - mean) * rs * g0.z + b0.z);
    o0.w = elu((a.w - mean) * rs * g0.w + b0.w);
    o1.x = elu((b.x - mean) * rs * g1.x + b1.x);
    o1.y = elu((b.y - mean) * rs * g1.y + b1.y);
    o1.z = elu((b.z - mean) * rs * g1.z + b1.z);
    o1.w = elu((b.w - mean) * rs * g1.w + b1.w);
    *(float4*)&o[(size_t)n * HID + lane * 4] = o0;
    *(float4*)&o[(size_t)n * HID + 128 + lane * 4] = o1;
}

// ---------------- pooling ----------------
__global__ void k_graph_starts(const int* __restrict__ batch) {
    int n = blockIdx.x * blockDim.x + threadIdx.x;
    if (n >= NN) return;
    int b = batch[n];
    int bp = (n == 0) ? -1 : batch[n - 1];
    for (int g = bp + 1; g <= b; g++) g_gstart[g] = n;
    if (n == NN - 1)
        for (int g = b + 1; g <= NG; g++) g_gstart[g] = NN;
}

__global__ void k_zero_float(float* p, int n) {
    int i = blockIdx.x * blockDim.x + threadIdx.x;
    if (i < n) p[i] = 0.f;
}

__global__ void k_pool_partial(const float* __restrict__ embp, int fallback_sel,
                               float* __restrict__ out) {
    const float* emb = embp ? embp : selbuf(fallback_sel);
    int g = blockIdx.x;
    int part = blockIdx.y;
    int c = threadIdx.x;
    int s = g_gstart[g], e = g_gstart[g + 1];
    int cnt = e - s;
    if (cnt <= 0) return;
    int chunk = (cnt + gridDim.y - 1) / gridDim.y;
    int ps = s + part * chunk;
    int pe = min(ps + chunk, e);
    if (ps >= pe) return;
    float acc = 0.f;
    for (int n = ps; n < pe; n++) acc += emb[n * HID + c];
    atomicAdd(&out[g * HID + c], acc);
}

__global__ void k_pool_final(float* __restrict__ out) {
    int g = blockIdx.x;
    int c = threadIdx.x;
    float cnt = (float)(g_gstart[g + 1] - g_gstart[g]);
    out[g * HID + c] /= fmaxf(cnt, 1.f);
}

// ---------------- launch ----------------
extern "C" void kernel_launch(void* const* d_in, const int* in_sizes, int n_in,
                              void* d_out, int out_size) {
    const float* x = (const float*)d_in[0];
    const int* edge_index = (const int*)d_in[1];   // int32
    const float* edge_attr = (const float*)d_in[2];
    const int* batch = (const int*)d_in[3];        // int32
    const float* x_W_in = (const float*)d_in[4];
    const float* b_in = (const float*)d_in[5];
    const float* ln_in_g = (const float*)d_in[6];
    const float* ln_in_b = (const float*)d_in[7];
    const float* W_gat = (const float*)d_in[8];
    const float* b_gat = (const float*)d_in[9];
    const float* W_e = (const float*)d_in[10];
    const float* a_src = (const float*)d_in[11];
    const float* a_dst = (const float*)d_in[12];
    const float* a_edge = (const float*)d_in[13];
    const float* W_out = (const float*)d_in[14];
    const float* b_out = (const float*)d_in[15];
    const float* ln_out_g = (const float*)d_in[16];
    const float* ln_out_b = (const float*)d_in[17];

    const int* src = edge_index;
    const int* dst = edge_index + NE;

    float* out = (float*)d_out;
    float* graph_out = nullptr;
    float* node_out = nullptr;
    if (out_size >= NG * HID + NN * HID) {
        graph_out = out;
        node_out = out + NG * HID;
    } else if (out_size >= NN * HID) {
        node_out = out;
    } else {
        graph_out = out;
    }

    const int EB = (NE + 255) / 256;
    const int NB = (NN + 255) / 256;
    const int NPARTS = (NN + 1023) / 1024;  // 49
    const int WS_B = (HID * HID + 255) / 256;
    const int SD_B = (NN * NHEADS + 7) / 8 + 1;  // +1: fused edge_coef block
    dim3 gemm_grid((NN + GM - 1) / GM, HID / GN);  // (782, 2)

    // Launch order keeps layer-0 k_wmma_gemm at index 3 (ncu window).
    k_input_proj<<<NN / 8, 256>>>(x, x_W_in, b_in, ln_in_g, ln_in_b); // 0
    k_zero_cursor<<<NB, 256>>>();                                    // 1
    k_wsplit<<<WS_B, 256>>>(W_gat);                                  // 2 (layer 0 W)
    k_wmma_gemm<<<gemm_grid, 128>>>(0, b_gat);                       // 3 (layer 0)
    k_count_deg<<<EB, 256>>>(dst);                                   // 4
    k_scan1<<<NPARTS, 1024>>>();                                     // 5
    k_scan2<<<1, 64>>>(NPARTS);                                      // 6
    k_scan3<<<NB, 256>>>();                                          // 7
    k_scatter<<<EB, 256>>>(src, dst, edge_attr);                     // 8

    int cur = 0;  // 0 = bufA, 1 = bufB
    for (int l = 0; l < NLAYERS; l++) {
        int nxt = 1 - cur;
        const float* Wl = W_gat + l * HID * HID;
        const float* bl = b_gat + l * HID;
        const float* Wel = W_e + l * EDIM * HID;
        const float* asl = a_src + l * NHEADS * HD;
        const float* adl = a_dst + l * NHEADS * HD;
        const float* ael = a_edge + l * NHEADS * HD;

        if (l > 0) {
            k_wsplit<<<WS_B, 256>>>(Wl);
            k_wmma_gemm<<<gemm_grid, 128>>>(cur, bl);
        }
        k_sdots<<<SD_B, 256>>>(asl, adl, Wel, ael);
        k_logit_stats<<<(NN + 7) / 8, 256>>>();
        k_aggregate<<<NN / 4, 256>>>(cur, nxt);
        cur = nxt;
    }

    // ---- output projection + LN + ELU ----
    k_wsplit<<<WS_B, 256>>>(W_out);
    k_wmma_gemm<<<gemm_grid, 128>>>(cur, b_out);
    int fsel = 1 - cur;
    k_ln_out<<<NN / 8, 256>>>(ln_out_g, ln_out_b, node_out, fsel);

    // ---- global mean pool ----
    if (graph_out) {
        k_graph_starts<<<NB, 256>>>(batch);
        k_zero_float<<<(NG * HID + 255) / 256, 256>>>(graph_out, NG * HID);
        dim3 pg(NG, 16);
        k_pool_partial<<<pg, 256>>>(node_out, fsel, graph_out);
        k_pool_final<<<NG, 256>>>(graph_out);
    }
}